// round 6
// baseline (speedup 1.0000x reference)
#include <cuda_runtime.h>
#include <math.h>
#include <stdint.h>

// Problem constants
#define Bc 2
#define Tc 16
#define Nc 256
#define Mc 1152
#define Hc 16
#define Dc 72
#define ROWS 8192        // B*T*N
#define M3 3456
#define FFD 4608
#define ADA 6912
#define QK_SCALE 0.11785113019775793f   // 72^-0.5
#define LN10000 9.210340371976184f

// tcgen05 only exists on the arch-specific ("a") targets. The harness also
// compiles a generic compute_103 PTX pass; give that pass an FFMA fallback.
#if defined(__CUDA_ARCH_FEAT_SM103_ALL) || defined(__CUDA_ARCH_FEAT_SM100_ALL) || defined(__CUDA_ARCH_FEAT_SM101_ALL)
#define HAS_TCGEN05 1
#else
#define HAS_TCGEN05 0
#endif

// ---------------- PTX helpers ----------------
__device__ __forceinline__ uint32_t smem_u32(const void* p) {
    uint32_t a;
    asm("{ .reg .u64 t; cvta.to.shared.u64 t, %1; cvt.u32.u64 %0, t; }" : "=r"(a) : "l"(p));
    return a;
}
__device__ __forceinline__ uint32_t elect1() {
    uint32_t p;
    asm volatile("{\n\t.reg .pred p;\n\telect.sync _|p, 0xFFFFFFFF;\n\tselp.b32 %0, 1, 0, p;\n\t}" : "=r"(p));
    return p;
}
#define MBARRIER_INIT(addr, count) \
    asm volatile("mbarrier.init.shared.b64 [%0], %1;" :: "r"((uint32_t)(addr)), "r"((uint32_t)(count)) : "memory")
#define MBARRIER_WAIT_PARITY(mbar_smem_addr, phase_parity) do { \
    uint32_t _mbar = (uint32_t)(mbar_smem_addr); \
    uint32_t _parity = (uint32_t)(phase_parity); \
    uint32_t _done; \
    asm volatile( \
        "{\n\t.reg .pred p;\n\t" \
        "mbarrier.try_wait.parity.acquire.cta.shared::cta.b64 p, [%1], %2;\n\t" \
        "selp.b32 %0, 1, 0, p;\n\t}" \
        : "=r"(_done) : "r"(_mbar), "r"(_parity) : "memory"); \
    if (!_done) { \
        asm volatile( \
            "{\n\t.reg .pred P1;\n\t" \
            "WAIT_LOOP_%=:\n\t" \
            "mbarrier.try_wait.parity.acquire.cta.shared::cta.b64 P1, [%0], %1, 0x989680;\n\t" \
            "@P1 bra.uni WAIT_DONE_%=;\n\t" \
            "bra.uni WAIT_LOOP_%=;\n\t" \
            "WAIT_DONE_%=:\n\t}" \
            :: "r"(_mbar), "r"(_parity) : "memory"); \
    } \
} while(0)

#if HAS_TCGEN05
#define TCGEN05_ALLOC(smem_result_addr, nCols) \
    asm volatile("tcgen05.alloc.cta_group::1.sync.aligned.shared::cta.b32 [%0], %1;" \
        :: "r"((uint32_t)(smem_result_addr)), "r"((uint32_t)(nCols)) : "memory")
#define TCGEN05_DEALLOC(tmem_addr, nCols) \
    asm volatile("tcgen05.dealloc.cta_group::1.sync.aligned.b32 %0, %1;" :: "r"(tmem_addr), "r"((uint32_t)(nCols)))
#define TCGEN05_RELINQUISH() \
    asm volatile("tcgen05.relinquish_alloc_permit.cta_group::1.sync.aligned;")
#define TCGEN05_COMMIT(mbar_smem_addr) \
    asm volatile("tcgen05.commit.cta_group::1.mbarrier::arrive::one.shared::cluster.b64 [%0];" \
        :: "r"((uint32_t)(mbar_smem_addr)) : "memory")
#define TCGEN05_FENCE_AFTER() asm volatile("tcgen05.fence::after_thread_sync;" ::: "memory")
#define TCGEN05_FENCE_BEFORE() asm volatile("tcgen05.fence::before_thread_sync;" ::: "memory")
#define TCGEN05_WAIT_LD() asm volatile("tcgen05.wait::ld.sync.aligned;" ::: "memory")
#define TCGEN05_LD_32X32B_X32(r, tmem_addr) \
    asm volatile( \
        "tcgen05.ld.sync.aligned.32x32b.x32.b32 " \
        "{%0, %1, %2, %3, %4, %5, %6, %7, " \
        " %8, %9, %10, %11, %12, %13, %14, %15, " \
        " %16, %17, %18, %19, %20, %21, %22, %23, " \
        " %24, %25, %26, %27, %28, %29, %30, %31}, [%32];" \
        : "=r"((r)[0]),  "=r"((r)[1]),  "=r"((r)[2]),  "=r"((r)[3]), \
          "=r"((r)[4]),  "=r"((r)[5]),  "=r"((r)[6]),  "=r"((r)[7]), \
          "=r"((r)[8]),  "=r"((r)[9]),  "=r"((r)[10]), "=r"((r)[11]), \
          "=r"((r)[12]), "=r"((r)[13]), "=r"((r)[14]), "=r"((r)[15]), \
          "=r"((r)[16]), "=r"((r)[17]), "=r"((r)[18]), "=r"((r)[19]), \
          "=r"((r)[20]), "=r"((r)[21]), "=r"((r)[22]), "=r"((r)[23]), \
          "=r"((r)[24]), "=r"((r)[25]), "=r"((r)[26]), "=r"((r)[27]), \
          "=r"((r)[28]), "=r"((r)[29]), "=r"((r)[30]), "=r"((r)[31]) \
        : "r"(tmem_addr))

__device__ __forceinline__ void mma_tf32_ss(uint32_t d, uint64_t ad, uint64_t bd,
                                            uint32_t idesc, bool en) {
    uint32_t e = en ? 1u : 0u;
    asm volatile(
        "{\n\t.reg .pred p;\n\t"
        "setp.ne.u32 p, %5, 0;\n\t"
        "tcgen05.mma.cta_group::1.kind::tf32 [%0], %1, %2, %3, {%4, %4, %4, %4}, p;\n\t}"
        :: "r"(d), "l"(ad), "l"(bd), "r"(idesc), "r"(0u), "r"(e) : "memory");
}
#endif // HAS_TCGEN05

static constexpr uint64_t SMEM_DESC_BASE_SW128 =
    (uint64_t(2)  << 61) | (uint64_t(1) << 46) | (uint64_t(64) << 32) | (uint64_t(1) << 16);
#define MAKE_SMEM_DESC(base_addr) \
    (SMEM_DESC_BASE_SW128 | ((uint64_t)((base_addr) >> 4) & 0x3FFF))
#define SMEM_SWIZZLE_128B(byte_offset) ((byte_offset) ^ (((byte_offset) >> 3) & 0x70))

__device__ __forceinline__ float hi_part(float v) {
    return __uint_as_float(__float_as_uint(v) & 0xffffe000u);
}

// ---------------- scratch ----------------
__device__ float g_silu[Bc * Mc];
__device__ float g_ada[Bc * ADA];
__device__ float g_ckr[Bc * Tc * Mc];
__device__ float g_cv [Bc * Tc * Mc];
__device__ float g_sk [Bc * Tc * Mc];
__device__ float g_sv [Bc * Tc * Mc];
__device__ float g_xt  [ROWS * Mc];
__device__ float g_qkv [ROWS * M3];
__device__ float g_tout[ROWS * Mc];
__device__ float g_proj[ROWS * Mc];
__device__ float g_mod [ROWS * Mc];
__device__ float g_satt[ROWS * Mc];
__device__ float g_h   [ROWS * FFD];

// ---------------- small kernels ----------------
__global__ void silu_k(const float* __restrict__ c4t, float* __restrict__ out) {
    int i = blockIdx.x * 256 + threadIdx.x;
    if (i < Bc * Mc) { float v = c4t[i]; out[i] = v / (1.f + expf(-v)); }
}

__global__ void ada_k(const float* __restrict__ s, const float* __restrict__ W,
                      const float* __restrict__ bias, float* __restrict__ out) {
    int col = blockIdx.x * 256 + threadIdx.x;
    int b = blockIdx.y;
    const float* sp = s + b * Mc;
    float a0 = 0.f, a1 = 0.f, a2 = 0.f, a3 = 0.f;
    float a4 = 0.f, a5 = 0.f, a6 = 0.f, a7 = 0.f;
    for (int k = 0; k < Mc; k += 8) {
        a0 = fmaf(sp[k + 0], __ldg(&W[(size_t)(k + 0) * ADA + col]), a0);
        a1 = fmaf(sp[k + 1], __ldg(&W[(size_t)(k + 1) * ADA + col]), a1);
        a2 = fmaf(sp[k + 2], __ldg(&W[(size_t)(k + 2) * ADA + col]), a2);
        a3 = fmaf(sp[k + 3], __ldg(&W[(size_t)(k + 3) * ADA + col]), a3);
        a4 = fmaf(sp[k + 4], __ldg(&W[(size_t)(k + 4) * ADA + col]), a4);
        a5 = fmaf(sp[k + 5], __ldg(&W[(size_t)(k + 5) * ADA + col]), a5);
        a6 = fmaf(sp[k + 6], __ldg(&W[(size_t)(k + 6) * ADA + col]), a6);
        a7 = fmaf(sp[k + 7], __ldg(&W[(size_t)(k + 7) * ADA + col]), a7);
    }
    out[(size_t)b * ADA + col] = ((a0 + a1) + (a2 + a3)) + ((a4 + a5) + (a6 + a7)) + bias[col];
}

__global__ void cproj4_k(const float* __restrict__ c,
                         const float* __restrict__ W0, const float* __restrict__ W1,
                         const float* __restrict__ W2, const float* __restrict__ W3,
                         float* __restrict__ o0, float* __restrict__ o1,
                         float* __restrict__ o2, float* __restrict__ o3) {
    int z = blockIdx.z;
    const float* W = (z == 0) ? W0 : (z == 1) ? W1 : (z == 2) ? W2 : W3;
    float* O = (z == 0) ? o0 : (z == 1) ? o1 : (z == 2) ? o2 : o3;
    int col = blockIdx.x * 128 + threadIdx.x;
    int r = blockIdx.y;
    const float* cp = c + (size_t)r * Mc;
    float a0 = 0.f, a1 = 0.f, a2 = 0.f, a3 = 0.f;
    for (int k = 0; k < Mc; k += 4) {
        a0 = fmaf(cp[k + 0], __ldg(&W[(size_t)(k + 0) * Mc + col]), a0);
        a1 = fmaf(cp[k + 1], __ldg(&W[(size_t)(k + 1) * Mc + col]), a1);
        a2 = fmaf(cp[k + 2], __ldg(&W[(size_t)(k + 2) * Mc + col]), a2);
        a3 = fmaf(cp[k + 3], __ldg(&W[(size_t)(k + 3) * Mc + col]), a3);
    }
    O[(size_t)r * Mc + col] = (a0 + a1) + (a2 + a3);
}

__global__ void rotc_k(float* __restrict__ ck, const int* __restrict__ f) {
    int r = blockIdx.x;
    int t = r & 15;
    float* p = ck + (size_t)r * Mc;
    float pos = (float)f[t];
    for (int idx = threadIdx.x; idx < Hc * 36; idx += 256) {
        int hh = idx / 36, i = idx - hh * 36;
        float inv = expf(-LN10000 * (float)(2 * i) * (1.f / 72.f));
        float ang = pos * inv;
        float cs = cosf(ang), sn = sinf(ang);
        int base = hh * 72 + 2 * i;
        float a = p[base], b = p[base + 1];
        p[base]     = a * cs - b * sn;
        p[base + 1] = b * cs + a * sn;
    }
}

__global__ __launch_bounds__(256)
void ln1_k(const float* __restrict__ x, const float* __restrict__ w,
           const float* __restrict__ bz, float* __restrict__ out) {
    __shared__ float row[Mc];
    __shared__ float red[256];
    int r = blockIdx.x, tid = threadIdx.x;
    const float* xp = x + (size_t)r * Mc;
    float s = 0.f;
    for (int c = tid; c < Mc; c += 256) { float v = xp[c]; row[c] = v; s += v; }
    red[tid] = s; __syncthreads();
    for (int o = 128; o > 0; o >>= 1) { if (tid < o) red[tid] += red[tid + o]; __syncthreads(); }
    float mu = red[0] * (1.f / Mc);
    __syncthreads();
    float s2 = 0.f;
    for (int c = tid; c < Mc; c += 256) { float d = row[c] - mu; s2 += d * d; }
    red[tid] = s2; __syncthreads();
    for (int o = 128; o > 0; o >>= 1) { if (tid < o) red[tid] += red[tid + o]; __syncthreads(); }
    float rstd = rsqrtf(red[0] * (1.f / Mc) + 1e-5f);
    int b = r >> 12, t = (r >> 8) & 15, n = r & 255;
    float* op = out + ((size_t)(((b << 8) + n) * 16 + t)) * Mc;
    for (int c = tid; c < Mc; c += 256) op[c] = (row[c] - mu) * rstd * w[c] + bz[c];
}

__global__ __launch_bounds__(256)
void lnmod_k(const float* __restrict__ in, const float* __restrict__ ada,
             int shOff, int scOff, float eps, float* __restrict__ out) {
    __shared__ float row[Mc];
    __shared__ float red[256];
    int r = blockIdx.x, tid = threadIdx.x;
    const float* xp = in + (size_t)r * Mc;
    float s = 0.f;
    for (int c = tid; c < Mc; c += 256) { float v = xp[c]; row[c] = v; s += v; }
    red[tid] = s; __syncthreads();
    for (int o = 128; o > 0; o >>= 1) { if (tid < o) red[tid] += red[tid + o]; __syncthreads(); }
    float mu = red[0] * (1.f / Mc);
    __syncthreads();
    float s2 = 0.f;
    for (int c = tid; c < Mc; c += 256) { float d = row[c] - mu; s2 += d * d; }
    red[tid] = s2; __syncthreads();
    for (int o = 128; o > 0; o >>= 1) { if (tid < o) red[tid] += red[tid + o]; __syncthreads(); }
    float rstd = rsqrtf(red[0] * (1.f / Mc) + eps);
    int b = r >> 12;
    const float* sh = ada + (size_t)b * ADA + shOff;
    const float* sc = ada + (size_t)b * ADA + scOff;
    float* op = out + (size_t)r * Mc;
    for (int c = tid; c < Mc; c += 256)
        op[c] = (row[c] - mu) * rstd * (1.f + sc[c]) + sh[c];
}

// ---------------- GEMM (tcgen05 tf32x3 on sm_103a; FFMA fallback elsewhere) ----------------
// C[8192, Ncols] = A[8192, Kdim] @ W[Kdim, Ncols], 128x128 tile per CTA.
// EPI: 0 plain | 1 gelu(acc+bias) | 2 C += gate*(acc+bias) | 3 resid+acc+bias w/ A row permute
#define TK 32
#define GEMM_SMEM 132096

template<int EPI>
__global__ __launch_bounds__(256)
void tc_gemm(const float* __restrict__ A, const float* __restrict__ W,
             float* __restrict__ C, int Ncols, int Kdim,
             const float* __restrict__ bias, const float* __restrict__ resid,
             const float* __restrict__ gate) {
    extern __shared__ char smem[];
    int tid = threadIdx.x;
#if HAS_TCGEN05
    uint32_t sb = smem_u32(smem);
    int wid = tid >> 5, lane = tid & 31;
    const int row0 = blockIdx.y * 128, col0 = blockIdx.x * 128;

    if (tid == 0) {
        MBARRIER_INIT(sb + 16, 1);
        MBARRIER_INIT(sb + 32, 1);
        MBARRIER_INIT(sb + 48, 1);
    }
    if (wid == 0) TCGEN05_ALLOC(sb + 0, 128);
    __syncthreads();
    uint32_t tmem;
    asm volatile("ld.shared.b32 %0, [%1];" : "=r"(tmem) : "r"(sb));

    const uint32_t idesc = (1u << 4) | (2u << 7) | (2u << 10) | (16u << 17) | (8u << 24);
    int nch = Kdim / TK;

    for (int i = 0; i < nch; i++) {
        int p = i & 1;
        char* buf = smem + 1024 + p * 65536;
        if (i >= 2) { MBARRIER_WAIT_PARITY(sb + 16 + p * 16, ((i >> 1) - 1) & 1); }
#pragma unroll
        for (int it = 0; it < 16; it++) {
            int idx = it * 256 + tid;
            int r = idx >> 5, k = idx & 31;
            int gr = row0 + r;
            if (EPI == 3) { int bb = gr >> 12, tt = (gr >> 8) & 15, nn = gr & 255; gr = ((bb << 8) + nn) * 16 + tt; }
            float v = __ldg(&A[(size_t)gr * Kdim + i * TK + k]);
            float h = hi_part(v);
            uint32_t off = SMEM_SWIZZLE_128B((uint32_t)(r * 128 + k * 4));
            *(float*)(buf + off) = h;
            *(float*)(buf + 16384 + off) = v - h;
        }
#pragma unroll
        for (int it = 0; it < 16; it++) {
            int idx = it * 256 + tid;
            int k = idx >> 7, n = idx & 127;
            float v = __ldg(&W[(size_t)(i * TK + k) * Ncols + col0 + n]);
            float h = hi_part(v);
            uint32_t off = SMEM_SWIZZLE_128B((uint32_t)(n * 128 + k * 4));
            *(float*)(buf + 32768 + off) = h;
            *(float*)(buf + 49152 + off) = v - h;
        }
        __syncthreads();
        if (wid == 0 && elect1()) {
            asm volatile("fence.proxy.async.shared::cta;" ::: "memory");
            uint32_t bbase = sb + 1024 + p * 65536;
            uint64_t dAh = MAKE_SMEM_DESC(bbase);
            uint64_t dAl = MAKE_SMEM_DESC(bbase + 16384);
            uint64_t dBh = MAKE_SMEM_DESC(bbase + 32768);
            uint64_t dBl = MAKE_SMEM_DESC(bbase + 49152);
#pragma unroll
            for (int k4 = 0; k4 < 4; k4++) mma_tf32_ss(tmem, dAh + k4 * 2, dBh + k4 * 2, idesc, !(i == 0 && k4 == 0));
#pragma unroll
            for (int k4 = 0; k4 < 4; k4++) mma_tf32_ss(tmem, dAh + k4 * 2, dBl + k4 * 2, idesc, true);
#pragma unroll
            for (int k4 = 0; k4 < 4; k4++) mma_tf32_ss(tmem, dAl + k4 * 2, dBh + k4 * 2, idesc, true);
            TCGEN05_COMMIT(sb + 16 + p * 16);
        }
    }
    if (wid == 0 && elect1()) TCGEN05_COMMIT(sb + 48);
    MBARRIER_WAIT_PARITY(sb + 48, 0);
    TCGEN05_FENCE_AFTER();

    // epilogue: TMEM -> smem staging (conflict-free, stride 129 floats)
    {
        uint32_t regs[64];
        int wi = wid & 3;
        int c0 = (wid >> 2) * 64;
        TCGEN05_LD_32X32B_X32(regs, tmem + c0);
        TCGEN05_LD_32X32B_X32(regs + 32, tmem + c0 + 32);
        TCGEN05_WAIT_LD();
        TCGEN05_FENCE_BEFORE();
        int row = wi * 32 + lane;
        float* st = (float*)(smem + 1024);
#pragma unroll
        for (int j = 0; j < 64; j++) st[row * 129 + c0 + j] = __uint_as_float(regs[j]);
    }
    __syncthreads();
    if (wid == 0) { TCGEN05_RELINQUISH(); TCGEN05_DEALLOC(tmem, 128); }

    const float* st = (const float*)(smem + 1024);
#pragma unroll
    for (int it = 0; it < 16; it++) {
        int idx = it * 256 + tid;
        int r = idx >> 5, q = idx & 31;
        int grow = row0 + r;
        int gcol = col0 + q * 4;
        float v0 = st[r * 129 + q * 4 + 0];
        float v1 = st[r * 129 + q * 4 + 1];
        float v2 = st[r * 129 + q * 4 + 2];
        float v3 = st[r * 129 + q * 4 + 3];
        size_t o = (size_t)grow * Ncols + gcol;
        if (EPI == 0) {
            *(float4*)&C[o] = make_float4(v0, v1, v2, v3);
        } else if (EPI == 1) {
            float4 w4;
            float* wp = &w4.x;
            float vv[4] = {v0, v1, v2, v3};
#pragma unroll
            for (int j = 0; j < 4; j++) {
                float v = vv[j] + bias[gcol + j];
                float u = 0.7978845608028654f * (v + 0.044715f * v * v * v);
                wp[j] = 0.5f * v * (1.f + tanhf(u));
            }
            *(float4*)&C[o] = w4;
        } else if (EPI == 2) {
            int bI = grow >> 12;
            float4 cur = *(const float4*)&C[o];
            const float* gp = gate + (size_t)bI * ADA + gcol;
            float b0 = bias ? bias[gcol + 0] : 0.f;
            float b1 = bias ? bias[gcol + 1] : 0.f;
            float b2 = bias ? bias[gcol + 2] : 0.f;
            float b3 = bias ? bias[gcol + 3] : 0.f;
            cur.x += gp[0] * (v0 + b0);
            cur.y += gp[1] * (v1 + b1);
            cur.z += gp[2] * (v2 + b2);
            cur.w += gp[3] * (v3 + b3);
            *(float4*)&C[o] = cur;
        } else {
            float4 res = *(const float4*)&resid[o];
            res.x += v0 + bias[gcol + 0];
            res.y += v1 + bias[gcol + 1];
            res.z += v2 + bias[gcol + 2];
            res.w += v3 + bias[gcol + 3];
            *(float4*)&C[o] = res;
        }
    }
#else
    // ---- generic-arch FFMA fallback (never selected on GB300; keeps all PTX passes valid) ----
    float (*As)[128] = (float(*)[128])smem;
    float (*Bs)[128] = (float(*)[128])(smem + 4096);
    int bc = blockIdx.x, br = blockIdx.y;
    int tr = tid >> 4, tcn = tid & 15;
    int aRow = tid >> 1;
    int aCol = (tid & 1) * 4;
    int bRow = tid >> 5;
    int bCol = (tid & 31) * 4;

    int aRowG = br * 128 + aRow;
    if (EPI == 3) {
        int bb = aRowG >> 12, tt = (aRowG >> 8) & 15, nn = aRowG & 255;
        aRowG = ((bb << 8) + nn) * 16 + tt;
    }
    const float* Ap = A + (size_t)aRowG * Kdim + aCol;
    const float* Wp = W + (size_t)bRow * Ncols + (size_t)bc * 128 + bCol;

    float acc[8][8];
#pragma unroll
    for (int i = 0; i < 8; i++)
#pragma unroll
        for (int j = 0; j < 8; j++) acc[i][j] = 0.f;

    for (int k0 = 0; k0 < Kdim; k0 += 8) {
        float4 av = *(const float4*)Ap;
        As[aCol + 0][aRow] = av.x;
        As[aCol + 1][aRow] = av.y;
        As[aCol + 2][aRow] = av.z;
        As[aCol + 3][aRow] = av.w;
        *(float4*)&Bs[bRow][bCol] = *(const float4*)Wp;
        __syncthreads();
#pragma unroll
        for (int k = 0; k < 8; k++) {
            float4 a0 = *(const float4*)&As[k][tr * 8];
            float4 a1 = *(const float4*)&As[k][tr * 8 + 4];
            float4 b0 = *(const float4*)&Bs[k][tcn * 8];
            float4 b1 = *(const float4*)&Bs[k][tcn * 8 + 4];
            float rm[8] = {a0.x, a0.y, a0.z, a0.w, a1.x, a1.y, a1.z, a1.w};
            float rn[8] = {b0.x, b0.y, b0.z, b0.w, b1.x, b1.y, b1.z, b1.w};
#pragma unroll
            for (int i = 0; i < 8; i++)
#pragma unroll
                for (int j = 0; j < 8; j++) acc[i][j] += rm[i] * rn[j];
        }
        __syncthreads();
        Ap += 8;
        Wp += (size_t)8 * Ncols;
    }

    int rowB = br * 128 + tr * 8;
    int colB = bc * 128 + tcn * 8;
#pragma unroll
    for (int i = 0; i < 8; i++) {
        int r = rowB + i;
        int bI = r >> 12;
        size_t rb = (size_t)r * Ncols;
#pragma unroll
        for (int j = 0; j < 8; j++) {
            int cI = colB + j;
            float v = acc[i][j];
            size_t idx = rb + cI;
            if (EPI == 0) {
                C[idx] = v;
            } else if (EPI == 1) {
                v += bias[cI];
                float u = 0.7978845608028654f * (v + 0.044715f * v * v * v);
                C[idx] = 0.5f * v * (1.f + tanhf(u));
            } else if (EPI == 2) {
                float bb = bias ? bias[cI] : 0.f;
                C[idx] = C[idx] + gate[(size_t)bI * ADA + cI] * (v + bb);
            } else {
                C[idx] = resid[idx] + v + bias[cI];
            }
        }
    }
#endif
}

// ---------------- temporal attention ----------------
__global__ __launch_bounds__(512)
void tattn_k(const float* __restrict__ qkv, const float* __restrict__ ckr,
             const float* __restrict__ cv, const int* __restrict__ f,
             float* __restrict__ out) {
    __shared__ float Qs[16][72];
    __shared__ float Ks[32][73];
    __shared__ float Vs[32][73];
    __shared__ float Ps[16][32];
    int blk = blockIdx.x;
    int h = blk & 15;
    int bn = blk >> 4;
    int b = bn >> 8;
    int tid = threadIdx.x;

    for (int idx = tid; idx < 16 * 72; idx += 512) {
        int t = idx / 72, d = idx - t * 72;
        size_t base = ((size_t)(bn * 16 + t)) * M3 + h * 72 + d;
        Qs[t][d]      = qkv[base] * QK_SCALE;
        Ks[16 + t][d] = qkv[base + Mc];
        Vs[16 + t][d] = qkv[base + 2 * Mc];
        size_t cb = ((size_t)(b * 16 + t)) * Mc + h * 72 + d;
        Ks[t][d] = ckr[cb];
        Vs[t][d] = cv[cb];
    }
    __syncthreads();
    for (int idx = tid; idx < 16 * 36; idx += 512) {
        int t = idx / 36, i = idx - t * 36;
        float inv = expf(-LN10000 * (float)(2 * i) * (1.f / 72.f));
        float ang = (float)f[t] * inv;
        float cs = cosf(ang), sn = sinf(ang);
        float q0 = Qs[t][2 * i], q1 = Qs[t][2 * i + 1];
        Qs[t][2 * i]     = q0 * cs - q1 * sn;
        Qs[t][2 * i + 1] = q1 * cs + q0 * sn;
        float k0 = Ks[16 + t][2 * i], k1 = Ks[16 + t][2 * i + 1];
        Ks[16 + t][2 * i]     = k0 * cs - k1 * sn;
        Ks[16 + t][2 * i + 1] = k1 * cs + k0 * sn;
    }
    __syncthreads();
    int w = tid >> 5, lane = tid & 31;
    float a = 0.f;
#pragma unroll
    for (int d = 0; d < 72; d++) a += Qs[w][d] * Ks[lane][d];
    float mx = a;
    for (int o = 16; o > 0; o >>= 1) mx = fmaxf(mx, __shfl_xor_sync(0xffffffffu, mx, o));
    float e = expf(a - mx);
    float s = e;
    for (int o = 16; o > 0; o >>= 1) s += __shfl_xor_sync(0xffffffffu, s, o);
    Ps[w][lane] = e / s;
    __syncthreads();
    for (int idx = tid; idx < 16 * 72; idx += 512) {
        int t = idx / 72, d = idx - t * 72;
        float o = 0.f;
#pragma unroll
        for (int j = 0; j < 32; j++) o += Ps[t][j] * Vs[j][d];
        out[((size_t)(bn * 16 + t)) * Mc + h * 72 + d] = o;
    }
}

// ---------------- spatial attention ----------------
__global__ __launch_bounds__(256)
void sattn_k(const float* __restrict__ qkv2, const float* __restrict__ sk,
             const float* __restrict__ sv, float* __restrict__ out) {
    __shared__ float Qs[32][72];
    __shared__ float L[32][257];
    int qt = blockIdx.x;
    int bth = blockIdx.y;
    int h = bth & 15, bt = bth >> 4;
    int tid = threadIdx.x;

    for (int idx = tid; idx < 32 * 72; idx += 256) {
        int q = idx / 72, d = idx - q * 72;
        int n = qt * 32 + q;
        Qs[q][d] = qkv2[((size_t)(bt * 256 + n)) * M3 + h * 72 + d] * QK_SCALE;
    }
    __syncthreads();
    int q = tid >> 3, g = tid & 7;
    for (int j = g; j < 257; j += 8) {
        const float* kp = (j == 0)
            ? (sk + (size_t)bt * Mc + h * 72)
            : (qkv2 + ((size_t)(bt * 256 + (j - 1))) * M3 + Mc + h * 72);
        float a = 0.f;
#pragma unroll
        for (int d = 0; d < 72; d++) a += Qs[q][d] * kp[d];
        L[q][j] = a;
    }
    float mx = -1e30f;
    for (int j = g; j < 257; j += 8) mx = fmaxf(mx, L[q][j]);
    for (int o = 4; o > 0; o >>= 1) mx = fmaxf(mx, __shfl_xor_sync(0xffffffffu, mx, o));
    float s = 0.f;
    for (int j = g; j < 257; j += 8) { float e = expf(L[q][j] - mx); L[q][j] = e; s += e; }
    for (int o = 4; o > 0; o >>= 1) s += __shfl_xor_sync(0xffffffffu, s, o);
    float invs = 1.f / s;
    __syncwarp();
    int d0 = g * 9;
    float o9[9];
#pragma unroll
    for (int i = 0; i < 9; i++) o9[i] = 0.f;
    for (int j = 0; j < 257; j++) {
        float p = L[q][j] * invs;
        const float* vp = (j == 0)
            ? (sv + (size_t)bt * Mc + h * 72 + d0)
            : (qkv2 + ((size_t)(bt * 256 + (j - 1))) * M3 + 2 * Mc + h * 72 + d0);
#pragma unroll
        for (int i = 0; i < 9; i++) o9[i] += p * vp[i];
    }
    int n = qt * 32 + q;
    float* op = out + ((size_t)(bt * 256 + n)) * Mc + h * 72 + d0;
#pragma unroll
    for (int i = 0; i < 9; i++) op[i] = o9[i];
}

// ---------------- launch ----------------
extern "C" void kernel_launch(void* const* d_in, const int* in_sizes, int n_in,
                              void* d_out, int out_size) {
    const float* x      = (const float*)d_in[0];
    const float* c4t    = (const float*)d_in[1];
    const float* c      = (const float*)d_in[2];
    const float* W_ada  = (const float*)d_in[3];
    const float* b_ada  = (const float*)d_in[4];
    const float* tn_w   = (const float*)d_in[5];
    const float* tn_b   = (const float*)d_in[6];
    const float* t_qkv  = (const float*)d_in[7];
    const float* t_k    = (const float*)d_in[8];
    const float* t_v    = (const float*)d_in[9];
    const float* t_out  = (const float*)d_in[10];
    const float* t_fc_w = (const float*)d_in[11];
    const float* t_fc_b = (const float*)d_in[12];
    const float* s_qkv  = (const float*)d_in[13];
    const float* s_k    = (const float*)d_in[14];
    const float* s_v    = (const float*)d_in[15];
    const float* s_out  = (const float*)d_in[16];
    const float* mlp_w1 = (const float*)d_in[17];
    const float* mlp_b1 = (const float*)d_in[18];
    const float* mlp_w2 = (const float*)d_in[19];
    const float* mlp_b2 = (const float*)d_in[20];
    const int*   f      = (const int*)d_in[21];
    float* out = (float*)d_out;

    float *p_silu, *p_ada, *p_ckr, *p_cv, *p_sk, *p_sv;
    float *p_xt, *p_qkv, *p_tout, *p_proj, *p_mod, *p_satt, *p_h;
    cudaGetSymbolAddress((void**)&p_silu, g_silu);
    cudaGetSymbolAddress((void**)&p_ada,  g_ada);
    cudaGetSymbolAddress((void**)&p_ckr,  g_ckr);
    cudaGetSymbolAddress((void**)&p_cv,   g_cv);
    cudaGetSymbolAddress((void**)&p_sk,   g_sk);
    cudaGetSymbolAddress((void**)&p_sv,   g_sv);
    cudaGetSymbolAddress((void**)&p_xt,   g_xt);
    cudaGetSymbolAddress((void**)&p_qkv,  g_qkv);
    cudaGetSymbolAddress((void**)&p_tout, g_tout);
    cudaGetSymbolAddress((void**)&p_proj, g_proj);
    cudaGetSymbolAddress((void**)&p_mod,  g_mod);
    cudaGetSymbolAddress((void**)&p_satt, g_satt);
    cudaGetSymbolAddress((void**)&p_h,    g_h);

    cudaFuncSetAttribute(tc_gemm<0>, cudaFuncAttributeMaxDynamicSharedMemorySize, GEMM_SMEM);
    cudaFuncSetAttribute(tc_gemm<1>, cudaFuncAttributeMaxDynamicSharedMemorySize, GEMM_SMEM);
    cudaFuncSetAttribute(tc_gemm<2>, cudaFuncAttributeMaxDynamicSharedMemorySize, GEMM_SMEM);
    cudaFuncSetAttribute(tc_gemm<3>, cudaFuncAttributeMaxDynamicSharedMemorySize, GEMM_SMEM);

    // adaLN params
    silu_k<<<9, 256>>>(c4t, p_silu);
    ada_k<<<dim3(27, 2), 256>>>(p_silu, W_ada, b_ada, p_ada);
    // conditioning projections (fused 4-in-1)
    cproj4_k<<<dim3(9, 32, 4), 128>>>(c, t_k, t_v, s_k, s_v, p_ckr, p_cv, p_sk, p_sv);
    rotc_k<<<32, 256>>>(p_ckr, f);
    // temporal branch
    ln1_k<<<ROWS, 256>>>(x, tn_w, tn_b, p_xt);
    tc_gemm<0><<<dim3(27, 64), 256, GEMM_SMEM>>>(p_xt, t_qkv, p_qkv, M3, Mc, nullptr, nullptr, nullptr);
    tattn_k<<<ROWS, 512>>>(p_qkv, p_ckr, p_cv, f, p_tout);
    tc_gemm<0><<<dim3(9, 64), 256, GEMM_SMEM>>>(p_tout, t_out, p_proj, Mc, Mc, nullptr, nullptr, nullptr);
    tc_gemm<3><<<dim3(9, 64), 256, GEMM_SMEM>>>(p_proj, t_fc_w, out, Mc, Mc, t_fc_b, x, nullptr);
    // spatial branch
    lnmod_k<<<ROWS, 256>>>(out, p_ada, 0, Mc, 1e-6f, p_mod);
    tc_gemm<0><<<dim3(27, 64), 256, GEMM_SMEM>>>(p_mod, s_qkv, p_qkv, M3, Mc, nullptr, nullptr, nullptr);
    sattn_k<<<dim3(8, 512), 256>>>(p_qkv, p_sk, p_sv, p_satt);
    tc_gemm<2><<<dim3(9, 64), 256, GEMM_SMEM>>>(p_satt, s_out, out, Mc, Mc, nullptr, nullptr, p_ada + 2 * Mc);
    // MLP
    lnmod_k<<<ROWS, 256>>>(out, p_ada, 3 * Mc, 4 * Mc, 1e-6f, p_mod);
    tc_gemm<1><<<dim3(36, 64), 256, GEMM_SMEM>>>(p_mod, mlp_w1, p_h, FFD, Mc, mlp_b1, nullptr, nullptr);
    tc_gemm<2><<<dim3(9, 64), 256, GEMM_SMEM>>>(p_h, mlp_w2, out, Mc, FFD, mlp_b2, nullptr, p_ada + 5 * Mc);
}

// round 12
// speedup vs baseline: 1.9740x; 1.9740x over previous
#include <cuda_runtime.h>
#include <math.h>
#include <stdint.h>

#define Bc 2
#define Tc 16
#define Nc 256
#define Mc 1152
#define Hc 16
#define ROWS 8192
#define M3 3456
#define FFD 4608
#define ADA 6912
#define QK_SCALE 0.11785113019775793f
#define LN10000 9.210340371976184f

#if defined(__CUDA_ARCH_FEAT_SM103_ALL) || defined(__CUDA_ARCH_FEAT_SM100_ALL) || defined(__CUDA_ARCH_FEAT_SM101_ALL)
#define HAS_TCGEN05 1
#else
#define HAS_TCGEN05 0
#endif

__device__ __forceinline__ uint32_t smem_u32(const void* p) {
    uint32_t a;
    asm("{ .reg .u64 t; cvta.to.shared.u64 t, %1; cvt.u32.u64 %0, t; }" : "=r"(a) : "l"(p));
    return a;
}
__device__ __forceinline__ uint32_t elect1() {
    uint32_t p;
    asm volatile("{\n\t.reg .pred p;\n\telect.sync _|p, 0xFFFFFFFF;\n\tselp.b32 %0, 1, 0, p;\n\t}" : "=r"(p));
    return p;
}
#define MBARRIER_INIT(addr, count) \
    asm volatile("mbarrier.init.shared.b64 [%0], %1;" :: "r"((uint32_t)(addr)), "r"((uint32_t)(count)) : "memory")
#define MBARRIER_WAIT_PARITY(a, ph) do { \
    uint32_t _m = (uint32_t)(a), _p = (uint32_t)(ph), _d; \
    asm volatile("{\n\t.reg .pred p;\n\tmbarrier.try_wait.parity.acquire.cta.shared::cta.b64 p, [%1], %2;\n\tselp.b32 %0, 1, 0, p;\n\t}" : "=r"(_d) : "r"(_m), "r"(_p) : "memory"); \
    if (!_d) { \
        asm volatile("{\n\t.reg .pred P1;\n\tWL_%=:\n\tmbarrier.try_wait.parity.acquire.cta.shared::cta.b64 P1, [%0], %1, 0x989680;\n\t@P1 bra.uni WD_%=;\n\tbra.uni WL_%=;\n\tWD_%=:\n\t}" :: "r"(_m), "r"(_p) : "memory"); \
    } \
} while(0)

#if HAS_TCGEN05
#define TCGEN05_ALLOC(a, n)   asm volatile("tcgen05.alloc.cta_group::1.sync.aligned.shared::cta.b32 [%0], %1;" :: "r"((uint32_t)(a)), "r"((uint32_t)(n)) : "memory")
#define TCGEN05_DEALLOC(t, n) asm volatile("tcgen05.dealloc.cta_group::1.sync.aligned.b32 %0, %1;" :: "r"(t), "r"((uint32_t)(n)))
#define TCGEN05_RELINQUISH()  asm volatile("tcgen05.relinquish_alloc_permit.cta_group::1.sync.aligned;")
#define TCGEN05_COMMIT(a)     asm volatile("tcgen05.commit.cta_group::1.mbarrier::arrive::one.shared::cluster.b64 [%0];" :: "r"((uint32_t)(a)) : "memory")
#define TCGEN05_FENCE_AFTER() asm volatile("tcgen05.fence::after_thread_sync;" ::: "memory")
#define TCGEN05_WAIT_LD()     asm volatile("tcgen05.wait::ld.sync.aligned;" ::: "memory")
#define TCGEN05_LD_X32(r, t) \
    asm volatile("tcgen05.ld.sync.aligned.32x32b.x32.b32 " \
        "{%0, %1, %2, %3, %4, %5, %6, %7, %8, %9, %10, %11, %12, %13, %14, %15, " \
        " %16, %17, %18, %19, %20, %21, %22, %23, %24, %25, %26, %27, %28, %29, %30, %31}, [%32];" \
        : "=r"((r)[0]), "=r"((r)[1]), "=r"((r)[2]), "=r"((r)[3]), "=r"((r)[4]), "=r"((r)[5]), "=r"((r)[6]), "=r"((r)[7]), \
          "=r"((r)[8]), "=r"((r)[9]), "=r"((r)[10]), "=r"((r)[11]), "=r"((r)[12]), "=r"((r)[13]), "=r"((r)[14]), "=r"((r)[15]), \
          "=r"((r)[16]), "=r"((r)[17]), "=r"((r)[18]), "=r"((r)[19]), "=r"((r)[20]), "=r"((r)[21]), "=r"((r)[22]), "=r"((r)[23]), \
          "=r"((r)[24]), "=r"((r)[25]), "=r"((r)[26]), "=r"((r)[27]), "=r"((r)[28]), "=r"((r)[29]), "=r"((r)[30]), "=r"((r)[31]) \
        : "r"(t))
__device__ __forceinline__ void mma_tf32_ss(uint32_t d, uint64_t ad, uint64_t bd, uint32_t idesc, bool en) {
    uint32_t e = en ? 1u : 0u;
    asm volatile("{\n\t.reg .pred p;\n\tsetp.ne.u32 p, %5, 0;\n\t"
        "tcgen05.mma.cta_group::1.kind::tf32 [%0], %1, %2, %3, {%4, %4, %4, %4}, p;\n\t}"
        :: "r"(d), "l"(ad), "l"(bd), "r"(idesc), "r"(0u), "r"(e) : "memory");
}
#endif

static constexpr uint64_t DESC_BASE =
    (uint64_t(2) << 61) | (uint64_t(1) << 46) | (uint64_t(64) << 32) | (uint64_t(1) << 16);
#define MK_DESC(a) (DESC_BASE | ((uint64_t)((a) >> 4) & 0x3FFF))
#define SWZ(o) ((o) ^ (((o) >> 3) & 0x70))

// ---------------- scratch ----------------
__device__ float g_silu[Bc * Mc];
__device__ float g_ada[Bc * ADA];
__device__ float g_ckr[Bc * Tc * Mc];
__device__ float g_cv [Bc * Tc * Mc];
__device__ float g_sk [Bc * Tc * Mc];
__device__ float g_sv [Bc * Tc * Mc];
__device__ float g_xt  [ROWS * Mc];
__device__ float g_qkv [ROWS * M3];
__device__ float g_tout[ROWS * Mc];
__device__ float g_proj[ROWS * Mc];
__device__ float g_mod [ROWS * Mc];
__device__ float g_satt[ROWS * Mc];
__device__ float g_h   [ROWS * FFD];
__device__ float gw_tqkv[2 * M3 * Mc];
__device__ float gw_sqkv[2 * M3 * Mc];
__device__ float gw_tout[2 * Mc * Mc];
__device__ float gw_tfc [2 * Mc * Mc];
__device__ float gw_sout[2 * Mc * Mc];
__device__ float gw_w1  [2 * FFD * Mc];
__device__ float gw_w2  [2 * Mc * FFD];

// ---------------- small kernels ----------------
__global__ void silu_k(const float* __restrict__ c4t, float* __restrict__ out) {
    int i = blockIdx.x * 256 + threadIdx.x;
    if (i < Bc * Mc) { float v = c4t[i]; out[i] = v / (1.f + expf(-v)); }
}

__global__ void ada_k(const float* __restrict__ s, const float* __restrict__ W,
                      const float* __restrict__ bias, float* __restrict__ out) {
    int col = blockIdx.x * 256 + threadIdx.x;
    int b = blockIdx.y;
    const float* sp = s + b * Mc;
    float a0 = 0.f, a1 = 0.f, a2 = 0.f, a3 = 0.f;
    for (int k = 0; k < Mc; k += 4) {
        a0 = fmaf(sp[k + 0], __ldg(&W[(size_t)(k + 0) * ADA + col]), a0);
        a1 = fmaf(sp[k + 1], __ldg(&W[(size_t)(k + 1) * ADA + col]), a1);
        a2 = fmaf(sp[k + 2], __ldg(&W[(size_t)(k + 2) * ADA + col]), a2);
        a3 = fmaf(sp[k + 3], __ldg(&W[(size_t)(k + 3) * ADA + col]), a3);
    }
    out[(size_t)b * ADA + col] = (a0 + a1) + (a2 + a3) + bias[col];
}

__global__ void cproj4_k(const float* __restrict__ c,
                         const float* __restrict__ W0, const float* __restrict__ W1,
                         const float* __restrict__ W2, const float* __restrict__ W3,
                         float* __restrict__ o0, float* __restrict__ o1,
                         float* __restrict__ o2, float* __restrict__ o3) {
    int z = blockIdx.z;
    const float* W = (z == 0) ? W0 : (z == 1) ? W1 : (z == 2) ? W2 : W3;
    float* O = (z == 0) ? o0 : (z == 1) ? o1 : (z == 2) ? o2 : o3;
    int col = blockIdx.x * 128 + threadIdx.x;
    int r = blockIdx.y;
    const float* cp = c + (size_t)r * Mc;
    float a0 = 0.f, a1 = 0.f, a2 = 0.f, a3 = 0.f;
    for (int k = 0; k < Mc; k += 4) {
        a0 = fmaf(cp[k + 0], __ldg(&W[(size_t)(k + 0) * Mc + col]), a0);
        a1 = fmaf(cp[k + 1], __ldg(&W[(size_t)(k + 1) * Mc + col]), a1);
        a2 = fmaf(cp[k + 2], __ldg(&W[(size_t)(k + 2) * Mc + col]), a2);
        a3 = fmaf(cp[k + 3], __ldg(&W[(size_t)(k + 3) * Mc + col]), a3);
    }
    O[(size_t)r * Mc + col] = (a0 + a1) + (a2 + a3);
}

__global__ void rotc_k(float* __restrict__ ck, const int* __restrict__ f) {
    int r = blockIdx.x;
    int t = r & 15;
    float* p = ck + (size_t)r * Mc;
    float pos = (float)f[t];
    for (int idx = threadIdx.x; idx < Hc * 36; idx += 256) {
        int hh = idx / 36, i = idx - hh * 36;
        float inv = expf(-LN10000 * (float)(2 * i) * (1.f / 72.f));
        float ang = pos * inv;
        float cs = cosf(ang), sn = sinf(ang);
        int base = hh * 72 + 2 * i;
        float a = p[base], b = p[base + 1];
        p[base]     = a * cs - b * sn;
        p[base + 1] = b * cs + a * sn;
    }
}

// W[K,N] -> out[0][N][K] = hi (tf32-exact), out[1][N][K] = lo
__global__ __launch_bounds__(256)
void wsplit_k(const float* __restrict__ W, int K, int N, float* __restrict__ out) {
    __shared__ float tile[32][33];
    int n0 = blockIdx.x * 32, k0 = blockIdx.y * 32;
    int tx = threadIdx.x & 31, ty = threadIdx.x >> 5;
    for (int j = ty; j < 32; j += 8)
        tile[j][tx] = W[(size_t)(k0 + j) * N + n0 + tx];
    __syncthreads();
    float* hi = out;
    float* lo = out + (size_t)N * K;
    for (int j = ty; j < 32; j += 8) {
        float v = tile[tx][j];
        float h = __uint_as_float(__float_as_uint(v) & 0xffffe000u);
        size_t o = (size_t)(n0 + j) * K + k0 + tx;
        hi[o] = h;
        lo[o] = v - h;
    }
}

__global__ __launch_bounds__(256)
void ln1_k(const float* __restrict__ x, const float* __restrict__ w,
           const float* __restrict__ bz, float* __restrict__ out) {
    __shared__ float row[Mc];
    __shared__ float red[256];
    int r = blockIdx.x, tid = threadIdx.x;
    const float* xp = x + (size_t)r * Mc;
    float s = 0.f;
    for (int c = tid; c < Mc; c += 256) { float v = xp[c]; row[c] = v; s += v; }
    red[tid] = s; __syncthreads();
    for (int o = 128; o > 0; o >>= 1) { if (tid < o) red[tid] += red[tid + o]; __syncthreads(); }
    float mu = red[0] * (1.f / Mc);
    __syncthreads();
    float s2 = 0.f;
    for (int c = tid; c < Mc; c += 256) { float d = row[c] - mu; s2 += d * d; }
    red[tid] = s2; __syncthreads();
    for (int o = 128; o > 0; o >>= 1) { if (tid < o) red[tid] += red[tid + o]; __syncthreads(); }
    float rstd = rsqrtf(red[0] * (1.f / Mc) + 1e-5f);
    int b = r >> 12, t = (r >> 8) & 15, n = r & 255;
    float* op = out + ((size_t)(((b << 8) + n) * 16 + t)) * Mc;
    for (int c = tid; c < Mc; c += 256) op[c] = (row[c] - mu) * rstd * w[c] + bz[c];
}

__global__ __launch_bounds__(256)
void lnmod_k(const float* __restrict__ in, const float* __restrict__ ada,
             int shOff, int scOff, float eps, float* __restrict__ out) {
    __shared__ float row[Mc];
    __shared__ float red[256];
    int r = blockIdx.x, tid = threadIdx.x;
    const float* xp = in + (size_t)r * Mc;
    float s = 0.f;
    for (int c = tid; c < Mc; c += 256) { float v = xp[c]; row[c] = v; s += v; }
    red[tid] = s; __syncthreads();
    for (int o = 128; o > 0; o >>= 1) { if (tid < o) red[tid] += red[tid + o]; __syncthreads(); }
    float mu = red[0] * (1.f / Mc);
    __syncthreads();
    float s2 = 0.f;
    for (int c = tid; c < Mc; c += 256) { float d = row[c] - mu; s2 += d * d; }
    red[tid] = s2; __syncthreads();
    for (int o = 128; o > 0; o >>= 1) { if (tid < o) red[tid] += red[tid + o]; __syncthreads(); }
    float rstd = rsqrtf(red[0] * (1.f / Mc) + eps);
    int b = r >> 12;
    const float* sh = ada + (size_t)b * ADA + shOff;
    const float* sc = ada + (size_t)b * ADA + scOff;
    float* op = out + (size_t)r * Mc;
    for (int c = tid; c < Mc; c += 256)
        op[c] = (row[c] - mu) * rstd * (1.f + sc[c]) + sh[c];
}

// ---------------- tcgen05 tf32x3 GEMM, 256x192 tile, preprocessed weights ----------------
// Wsp = [hi[N][K] ; lo[N][K]] fp32.  Stage: Ahi 0 (32K) Alo 32K Bhi 64K (24K) Blo 88K
#define STAGE 114688
#define GEMM_SMEM (1024 + 2 * STAGE)

template<int EPI>
__global__ __launch_bounds__(256)
void tc_gemm(const float* __restrict__ A, const float* __restrict__ Wsp,
             float* __restrict__ C, int Ncols, int Kdim,
             const float* __restrict__ bias, const float* __restrict__ resid,
             const float* __restrict__ gate) {
    extern __shared__ char smem[];
    int tid = threadIdx.x;
    const int row0 = blockIdx.y * 256, col0 = blockIdx.x * 192;
#if HAS_TCGEN05
    uint32_t sb = smem_u32(smem);
    int wid = tid >> 5, lane = tid & 31;
    const float* Bhi = Wsp;
    const float* Blo = Wsp + (size_t)Ncols * Kdim;

    if (tid == 0) { MBARRIER_INIT(sb + 16, 1); MBARRIER_INIT(sb + 32, 1); MBARRIER_INIT(sb + 48, 1); }
    if (wid == 0) TCGEN05_ALLOC(sb + 0, 512);
    __syncthreads();
    uint32_t tmem;
    asm volatile("ld.shared.b32 %0, [%1];" : "=r"(tmem) : "r"(sb));

    const uint32_t idesc = (1u << 4) | (2u << 7) | (2u << 10) | (24u << 17) | (8u << 24);
    int nch = Kdim >> 5;

    for (int i = 0; i < nch; i++) {
        int p = i & 1;
        char* buf = smem + 1024 + p * STAGE;
        if (i >= 2) { MBARRIER_WAIT_PARITY(sb + 16 + p * 16, ((i >> 1) - 1) & 1); }
        int k0 = i << 5;
        // A: 256 rows x 32 K floats = 2048 float4 units
#pragma unroll
        for (int it = 0; it < 8; it++) {
            int idx = it * 256 + tid;
            int r = idx >> 3, q = idx & 7;
            int gr = row0 + r;
            if (EPI == 3) { int bb = gr >> 12, tt = (gr >> 8) & 15, nn = gr & 255; gr = ((bb << 8) + nn) * 16 + tt; }
            float4 v = __ldg((const float4*)(A + (size_t)gr * Kdim + k0 + q * 4));
            float4 h;
            h.x = __uint_as_float(__float_as_uint(v.x) & 0xffffe000u);
            h.y = __uint_as_float(__float_as_uint(v.y) & 0xffffe000u);
            h.z = __uint_as_float(__float_as_uint(v.z) & 0xffffe000u);
            h.w = __uint_as_float(__float_as_uint(v.w) & 0xffffe000u);
            float4 l = make_float4(v.x - h.x, v.y - h.y, v.z - h.z, v.w - h.w);
            uint32_t off = SWZ((uint32_t)(r * 128 + q * 16));
            *(float4*)(buf + off) = h;
            *(float4*)(buf + 32768 + off) = l;
        }
        // B: 192 rows x 32 K floats = 1536 float4 units, pure copies
#pragma unroll
        for (int it = 0; it < 6; it++) {
            int idx = it * 256 + tid;
            int n = idx >> 3, q = idx & 7;
            size_t gof = (size_t)(col0 + n) * Kdim + k0 + q * 4;
            uint32_t off = SWZ((uint32_t)(n * 128 + q * 16));
            *(float4*)(buf + 65536 + off) = __ldg((const float4*)(Bhi + gof));
            *(float4*)(buf + 90112 + off) = __ldg((const float4*)(Blo + gof));
        }
        __syncthreads();
        if (wid == 0 && elect1()) {
            asm volatile("fence.proxy.async.shared::cta;" ::: "memory");
            uint32_t bb = sb + 1024 + p * STAGE;
            uint64_t dA0h = MK_DESC(bb),         dA1h = MK_DESC(bb + 16384);
            uint64_t dA0l = MK_DESC(bb + 32768), dA1l = MK_DESC(bb + 49152);
            uint64_t dBh  = MK_DESC(bb + 65536), dBl  = MK_DESC(bb + 90112);
#pragma unroll
            for (int k4 = 0; k4 < 4; k4++) {
                bool en = !(i == 0 && k4 == 0);
                mma_tf32_ss(tmem,       dA0h + 2 * k4, dBh + 2 * k4, idesc, en);
                mma_tf32_ss(tmem + 192, dA1h + 2 * k4, dBh + 2 * k4, idesc, en);
            }
#pragma unroll
            for (int k4 = 0; k4 < 4; k4++) {
                mma_tf32_ss(tmem,       dA0h + 2 * k4, dBl + 2 * k4, idesc, true);
                mma_tf32_ss(tmem + 192, dA1h + 2 * k4, dBl + 2 * k4, idesc, true);
                mma_tf32_ss(tmem,       dA0l + 2 * k4, dBh + 2 * k4, idesc, true);
                mma_tf32_ss(tmem + 192, dA1l + 2 * k4, dBh + 2 * k4, idesc, true);
            }
            TCGEN05_COMMIT(sb + 16 + p * 16);
        }
    }
    if (wid == 0 && elect1()) TCGEN05_COMMIT(sb + 48);
    MBARRIER_WAIT_PARITY(sb + 48, 0);
    TCGEN05_FENCE_AFTER();
    __syncthreads();

    // epilogue: 3 slabs of 64 cols; TMEM -> smem [256][65] -> float4 STG
    float* st = (float*)(smem + 1024);
    int half = wid >> 2, part = wid & 3;
#pragma unroll 1
    for (int s = 0; s < 3; s++) {
        int colb = s * 64;
        uint32_t regs[64];
        TCGEN05_LD_X32(regs, tmem + half * 192 + colb);
        TCGEN05_LD_X32(regs + 32, tmem + half * 192 + colb + 32);
        TCGEN05_WAIT_LD();
        int row = half * 128 + part * 32 + lane;
#pragma unroll
        for (int j = 0; j < 64; j++) st[row * 65 + j] = __uint_as_float(regs[j]);
        __syncthreads();
#pragma unroll 4
        for (int it = 0; it < 16; it++) {
            int idx = it * 256 + tid;
            int r = idx >> 4, q = idx & 15;
            int grow = row0 + r;
            int gcol = col0 + colb + q * 4;
            float v0 = st[r * 65 + q * 4 + 0];
            float v1 = st[r * 65 + q * 4 + 1];
            float v2 = st[r * 65 + q * 4 + 2];
            float v3 = st[r * 65 + q * 4 + 3];
            size_t o = (size_t)grow * Ncols + gcol;
            if (EPI == 0) {
                *(float4*)&C[o] = make_float4(v0, v1, v2, v3);
            } else if (EPI == 1) {
                float vv[4] = {v0, v1, v2, v3};
                float4 w4;
                float* wp = &w4.x;
#pragma unroll
                for (int j = 0; j < 4; j++) {
                    float v = vv[j] + bias[gcol + j];
                    float u = 0.7978845608028654f * (v + 0.044715f * v * v * v);
                    wp[j] = 0.5f * v * (1.f + tanhf(u));
                }
                *(float4*)&C[o] = w4;
            } else if (EPI == 2) {
                int bI = grow >> 12;
                float4 cur = *(const float4*)&C[o];
                const float* gp = gate + (size_t)bI * ADA + gcol;
                float b0 = bias ? bias[gcol + 0] : 0.f;
                float b1 = bias ? bias[gcol + 1] : 0.f;
                float b2 = bias ? bias[gcol + 2] : 0.f;
                float b3 = bias ? bias[gcol + 3] : 0.f;
                cur.x += gp[0] * (v0 + b0);
                cur.y += gp[1] * (v1 + b1);
                cur.z += gp[2] * (v2 + b2);
                cur.w += gp[3] * (v3 + b3);
                *(float4*)&C[o] = cur;
            } else {
                float4 res = *(const float4*)&resid[o];
                res.x += v0 + bias[gcol + 0];
                res.y += v1 + bias[gcol + 1];
                res.z += v2 + bias[gcol + 2];
                res.w += v3 + bias[gcol + 3];
                *(float4*)&C[o] = res;
            }
        }
        __syncthreads();
    }
    if (wid == 0) { TCGEN05_RELINQUISH(); TCGEN05_DEALLOC(tmem, 512); }
#else
    // generic-arch compile-only fallback
    const float* Bhi = Wsp;
    const float* Blo = Wsp + (size_t)Ncols * Kdim;
    for (int e = tid; e < 256 * 192; e += 256) {
        int r = e / 192, cI = e % 192;
        int grow = row0 + r;
        int ar = grow;
        if (EPI == 3) { int bb = ar >> 12, tt = (ar >> 8) & 15, nn = ar & 255; ar = ((bb << 8) + nn) * 16 + tt; }
        int gcol = col0 + cI;
        float acc = 0.f;
        for (int k = 0; k < Kdim; k++)
            acc += A[(size_t)ar * Kdim + k] * (Bhi[(size_t)gcol * Kdim + k] + Blo[(size_t)gcol * Kdim + k]);
        size_t o = (size_t)grow * Ncols + gcol;
        if (EPI == 0) C[o] = acc;
        else if (EPI == 1) {
            float v = acc + bias[gcol];
            float u = 0.7978845608028654f * (v + 0.044715f * v * v * v);
            C[o] = 0.5f * v * (1.f + tanhf(u));
        } else if (EPI == 2) {
            int bI = grow >> 12;
            float bbv = bias ? bias[gcol] : 0.f;
            C[o] = C[o] + gate[(size_t)bI * ADA + gcol] * (acc + bbv);
        } else {
            C[o] = resid[o] + acc + bias[gcol];
        }
    }
#endif
}

// ---------------- temporal attention ----------------
__global__ __launch_bounds__(512)
void tattn_k(const float* __restrict__ qkv, const float* __restrict__ ckr,
             const float* __restrict__ cv, const int* __restrict__ f,
             float* __restrict__ out) {
    __shared__ float Qs[16][72];
    __shared__ float Ks[32][73];
    __shared__ float Vs[32][73];
    __shared__ float Ps[16][32];
    int blk = blockIdx.x;
    int h = blk & 15;
    int bn = blk >> 4;
    int b = bn >> 8;
    int tid = threadIdx.x;
    for (int idx = tid; idx < 16 * 72; idx += 512) {
        int t = idx / 72, d = idx - t * 72;
        size_t base = ((size_t)(bn * 16 + t)) * M3 + h * 72 + d;
        Qs[t][d]      = qkv[base] * QK_SCALE;
        Ks[16 + t][d] = qkv[base + Mc];
        Vs[16 + t][d] = qkv[base + 2 * Mc];
        size_t cb = ((size_t)(b * 16 + t)) * Mc + h * 72 + d;
        Ks[t][d] = ckr[cb];
        Vs[t][d] = cv[cb];
    }
    __syncthreads();
    for (int idx = tid; idx < 16 * 36; idx += 512) {
        int t = idx / 36, i = idx - t * 36;
        float inv = expf(-LN10000 * (float)(2 * i) * (1.f / 72.f));
        float ang = (float)f[t] * inv;
        float cs = cosf(ang), sn = sinf(ang);
        float q0 = Qs[t][2 * i], q1 = Qs[t][2 * i + 1];
        Qs[t][2 * i]     = q0 * cs - q1 * sn;
        Qs[t][2 * i + 1] = q1 * cs + q0 * sn;
        float k0 = Ks[16 + t][2 * i], k1 = Ks[16 + t][2 * i + 1];
        Ks[16 + t][2 * i]     = k0 * cs - k1 * sn;
        Ks[16 + t][2 * i + 1] = k1 * cs + k0 * sn;
    }
    __syncthreads();
    int w = tid >> 5, lane = tid & 31;
    float a = 0.f;
#pragma unroll
    for (int d = 0; d < 72; d++) a += Qs[w][d] * Ks[lane][d];
    float mx = a;
    for (int o = 16; o > 0; o >>= 1) mx = fmaxf(mx, __shfl_xor_sync(0xffffffffu, mx, o));
    float e = expf(a - mx);
    float s = e;
    for (int o = 16; o > 0; o >>= 1) s += __shfl_xor_sync(0xffffffffu, s, o);
    Ps[w][lane] = e / s;
    __syncthreads();
    for (int idx = tid; idx < 16 * 72; idx += 512) {
        int t = idx / 72, d = idx - t * 72;
        float o = 0.f;
#pragma unroll
        for (int j = 0; j < 32; j++) o += Ps[t][j] * Vs[j][d];
        out[((size_t)(bn * 16 + t)) * Mc + h * 72 + d] = o;
    }
}

// ---------------- spatial attention ----------------
__global__ __launch_bounds__(256)
void sattn_k(const float* __restrict__ qkv2, const float* __restrict__ sk,
             const float* __restrict__ sv, float* __restrict__ out) {
    __shared__ float Qs[32][72];
    __shared__ float L[32][257];
    int qt = blockIdx.x;
    int bth = blockIdx.y;
    int h = bth & 15, bt = bth >> 4;
    int tid = threadIdx.x;
    for (int idx = tid; idx < 32 * 72; idx += 256) {
        int q = idx / 72, d = idx - q * 72;
        int n = qt * 32 + q;
        Qs[q][d] = qkv2[((size_t)(bt * 256 + n)) * M3 + h * 72 + d] * QK_SCALE;
    }
    __syncthreads();
    int q = tid >> 3, g = tid & 7;
    for (int j = g; j < 257; j += 8) {
        const float* kp = (j == 0)
            ? (sk + (size_t)bt * Mc + h * 72)
            : (qkv2 + ((size_t)(bt * 256 + (j - 1))) * M3 + Mc + h * 72);
        float a = 0.f;
#pragma unroll
        for (int d = 0; d < 72; d++) a += Qs[q][d] * kp[d];
        L[q][j] = a;
    }
    float mx = -1e30f;
    for (int j = g; j < 257; j += 8) mx = fmaxf(mx, L[q][j]);
    for (int o = 4; o > 0; o >>= 1) mx = fmaxf(mx, __shfl_xor_sync(0xffffffffu, mx, o));
    float s = 0.f;
    for (int j = g; j < 257; j += 8) { float e = expf(L[q][j] - mx); L[q][j] = e; s += e; }
    for (int o = 4; o > 0; o >>= 1) s += __shfl_xor_sync(0xffffffffu, s, o);
    float invs = 1.f / s;
    __syncwarp();
    int d0 = g * 9;
    float o9[9];
#pragma unroll
    for (int i = 0; i < 9; i++) o9[i] = 0.f;
    for (int j = 0; j < 257; j++) {
        float p = L[q][j] * invs;
        const float* vp = (j == 0)
            ? (sv + (size_t)bt * Mc + h * 72 + d0)
            : (qkv2 + ((size_t)(bt * 256 + (j - 1))) * M3 + 2 * Mc + h * 72 + d0);
#pragma unroll
        for (int i = 0; i < 9; i++) o9[i] += p * vp[i];
    }
    int n = qt * 32 + q;
    float* op = out + ((size_t)(bt * 256 + n)) * Mc + h * 72 + d0;
#pragma unroll
    for (int i = 0; i < 9; i++) op[i] = o9[i];
}

// ---------------- launch ----------------
extern "C" void kernel_launch(void* const* d_in, const int* in_sizes, int n_in,
                              void* d_out, int out_size) {
    const float* x      = (const float*)d_in[0];
    const float* c4t    = (const float*)d_in[1];
    const float* c      = (const float*)d_in[2];
    const float* W_ada  = (const float*)d_in[3];
    const float* b_ada  = (const float*)d_in[4];
    const float* tn_w   = (const float*)d_in[5];
    const float* tn_b   = (const float*)d_in[6];
    const float* t_qkv  = (const float*)d_in[7];
    const float* t_k    = (const float*)d_in[8];
    const float* t_v    = (const float*)d_in[9];
    const float* t_out  = (const float*)d_in[10];
    const float* t_fc_w = (const float*)d_in[11];
    const float* t_fc_b = (const float*)d_in[12];
    const float* s_qkv  = (const float*)d_in[13];
    const float* s_k    = (const float*)d_in[14];
    const float* s_v    = (const float*)d_in[15];
    const float* s_out  = (const float*)d_in[16];
    const float* mlp_w1 = (const float*)d_in[17];
    const float* mlp_b1 = (const float*)d_in[18];
    const float* mlp_w2 = (const float*)d_in[19];
    const float* mlp_b2 = (const float*)d_in[20];
    const int*   f      = (const int*)d_in[21];
    float* out = (float*)d_out;

    float *p_silu, *p_ada, *p_ckr, *p_cv, *p_sk, *p_sv;
    float *p_xt, *p_qkv, *p_tout, *p_proj, *p_mod, *p_satt, *p_h;
    float *w_tqkv, *w_sqkv, *w_tout, *w_tfc, *w_sout, *w_w1, *w_w2;
    cudaGetSymbolAddress((void**)&p_silu, g_silu);
    cudaGetSymbolAddress((void**)&p_ada,  g_ada);
    cudaGetSymbolAddress((void**)&p_ckr,  g_ckr);
    cudaGetSymbolAddress((void**)&p_cv,   g_cv);
    cudaGetSymbolAddress((void**)&p_sk,   g_sk);
    cudaGetSymbolAddress((void**)&p_sv,   g_sv);
    cudaGetSymbolAddress((void**)&p_xt,   g_xt);
    cudaGetSymbolAddress((void**)&p_qkv,  g_qkv);
    cudaGetSymbolAddress((void**)&p_tout, g_tout);
    cudaGetSymbolAddress((void**)&p_proj, g_proj);
    cudaGetSymbolAddress((void**)&p_mod,  g_mod);
    cudaGetSymbolAddress((void**)&p_satt, g_satt);
    cudaGetSymbolAddress((void**)&p_h,    g_h);
    cudaGetSymbolAddress((void**)&w_tqkv, gw_tqkv);
    cudaGetSymbolAddress((void**)&w_sqkv, gw_sqkv);
    cudaGetSymbolAddress((void**)&w_tout, gw_tout);
    cudaGetSymbolAddress((void**)&w_tfc,  gw_tfc);
    cudaGetSymbolAddress((void**)&w_sout, gw_sout);
    cudaGetSymbolAddress((void**)&w_w1,   gw_w1);
    cudaGetSymbolAddress((void**)&w_w2,   gw_w2);

    cudaFuncSetAttribute(tc_gemm<0>, cudaFuncAttributeMaxDynamicSharedMemorySize, GEMM_SMEM);
    cudaFuncSetAttribute(tc_gemm<1>, cudaFuncAttributeMaxDynamicSharedMemorySize, GEMM_SMEM);
    cudaFuncSetAttribute(tc_gemm<2>, cudaFuncAttributeMaxDynamicSharedMemorySize, GEMM_SMEM);
    cudaFuncSetAttribute(tc_gemm<3>, cudaFuncAttributeMaxDynamicSharedMemorySize, GEMM_SMEM);

    // weight preprocessing: transpose + tf32 hi/lo split
    wsplit_k<<<dim3(M3 / 32, Mc / 32), 256>>>(t_qkv, Mc, M3, w_tqkv);
    wsplit_k<<<dim3(M3 / 32, Mc / 32), 256>>>(s_qkv, Mc, M3, w_sqkv);
    wsplit_k<<<dim3(Mc / 32, Mc / 32), 256>>>(t_out, Mc, Mc, w_tout);
    wsplit_k<<<dim3(Mc / 32, Mc / 32), 256>>>(t_fc_w, Mc, Mc, w_tfc);
    wsplit_k<<<dim3(Mc / 32, Mc / 32), 256>>>(s_out, Mc, Mc, w_sout);
    wsplit_k<<<dim3(FFD / 32, Mc / 32), 256>>>(mlp_w1, Mc, FFD, w_w1);
    wsplit_k<<<dim3(Mc / 32, FFD / 32), 256>>>(mlp_w2, FFD, Mc, w_w2);

    // adaLN + conditioning
    silu_k<<<9, 256>>>(c4t, p_silu);
    ada_k<<<dim3(27, 2), 256>>>(p_silu, W_ada, b_ada, p_ada);
    cproj4_k<<<dim3(9, 32, 4), 128>>>(c, t_k, t_v, s_k, s_v, p_ckr, p_cv, p_sk, p_sv);
    rotc_k<<<32, 256>>>(p_ckr, f);
    // temporal branch
    ln1_k<<<ROWS, 256>>>(x, tn_w, tn_b, p_xt);
    tc_gemm<0><<<dim3(18, 32), 256, GEMM_SMEM>>>(p_xt, w_tqkv, p_qkv, M3, Mc, nullptr, nullptr, nullptr);
    tattn_k<<<ROWS, 512>>>(p_qkv, p_ckr, p_cv, f, p_tout);
    tc_gemm<0><<<dim3(6, 32), 256, GEMM_SMEM>>>(p_tout, w_tout, p_proj, Mc, Mc, nullptr, nullptr, nullptr);
    tc_gemm<3><<<dim3(6, 32), 256, GEMM_SMEM>>>(p_proj, w_tfc, out, Mc, Mc, t_fc_b, x, nullptr);
    // spatial branch
    lnmod_k<<<ROWS, 256>>>(out, p_ada, 0, Mc, 1e-6f, p_mod);
    tc_gemm<0><<<dim3(18, 32), 256, GEMM_SMEM>>>(p_mod, w_sqkv, p_qkv, M3, Mc, nullptr, nullptr, nullptr);
    sattn_k<<<dim3(8, 512), 256>>>(p_qkv, p_sk, p_sv, p_satt);
    tc_gemm<2><<<dim3(6, 32), 256, GEMM_SMEM>>>(p_satt, w_sout, out, Mc, Mc, nullptr, nullptr, p_ada + 2 * Mc);
    // MLP
    lnmod_k<<<ROWS, 256>>>(out, p_ada, 3 * Mc, 4 * Mc, 1e-6f, p_mod);
    tc_gemm<1><<<dim3(24, 32), 256, GEMM_SMEM>>>(p_mod, w_w1, p_h, FFD, Mc, mlp_b1, nullptr, nullptr);
    tc_gemm<2><<<dim3(6, 32), 256, GEMM_SMEM>>>(p_h, w_w2, out, Mc, FFD, mlp_b2, nullptr, p_ada + 5 * Mc);
}

// round 14
// speedup vs baseline: 2.2226x; 1.1259x over previous
#include <cuda_runtime.h>
#include <math.h>
#include <stdint.h>

#define Bc 2
#define Tc 16
#define Nc 256
#define Mc 1152
#define Hc 16
#define ROWS 8192
#define M3 3456
#define FFD 4608
#define ADA 6912
#define QK_SCALE 0.11785113019775793f
#define LN10000 9.210340371976184f

#if defined(__CUDA_ARCH_FEAT_SM103_ALL) || defined(__CUDA_ARCH_FEAT_SM100_ALL) || defined(__CUDA_ARCH_FEAT_SM101_ALL)
#define HAS_TCGEN05 1
#else
#define HAS_TCGEN05 0
#endif

__device__ __forceinline__ uint32_t smem_u32(const void* p) {
    uint32_t a;
    asm("{ .reg .u64 t; cvta.to.shared.u64 t, %1; cvt.u32.u64 %0, t; }" : "=r"(a) : "l"(p));
    return a;
}
__device__ __forceinline__ uint32_t elect1() {
    uint32_t p;
    asm volatile("{\n\t.reg .pred p;\n\telect.sync _|p, 0xFFFFFFFF;\n\tselp.b32 %0, 1, 0, p;\n\t}" : "=r"(p));
    return p;
}
__device__ __forceinline__ void split2(float v, float& h, float& l) {
    h = __uint_as_float(__float_as_uint(v) & 0xffffe000u);
    l = v - h;
}
#define MBARRIER_INIT(addr, count) \
    asm volatile("mbarrier.init.shared.b64 [%0], %1;" :: "r"((uint32_t)(addr)), "r"((uint32_t)(count)) : "memory")
#define MBARRIER_WAIT_PARITY(a, ph) do { \
    uint32_t _m = (uint32_t)(a), _p = (uint32_t)(ph), _d; \
    asm volatile("{\n\t.reg .pred p;\n\tmbarrier.try_wait.parity.acquire.cta.shared::cta.b64 p, [%1], %2;\n\tselp.b32 %0, 1, 0, p;\n\t}" : "=r"(_d) : "r"(_m), "r"(_p) : "memory"); \
    if (!_d) { \
        asm volatile("{\n\t.reg .pred P1;\n\tWL_%=:\n\tmbarrier.try_wait.parity.acquire.cta.shared::cta.b64 P1, [%0], %1, 0x989680;\n\t@P1 bra.uni WD_%=;\n\tbra.uni WL_%=;\n\tWD_%=:\n\t}" :: "r"(_m), "r"(_p) : "memory"); \
    } \
} while(0)
#define CP_ASYNC16(dst, src) \
    asm volatile("cp.async.cg.shared.global [%0], [%1], 16;" :: "r"((uint32_t)(dst)), "l"(src) : "memory")
#define CP_COMMIT() asm volatile("cp.async.commit_group;" ::: "memory")
#define CP_WAIT(n)  asm volatile("cp.async.wait_group %0;" :: "n"(n) : "memory")

#if HAS_TCGEN05
#define TCGEN05_ALLOC(a, n)   asm volatile("tcgen05.alloc.cta_group::1.sync.aligned.shared::cta.b32 [%0], %1;" :: "r"((uint32_t)(a)), "r"((uint32_t)(n)) : "memory")
#define TCGEN05_DEALLOC(t, n) asm volatile("tcgen05.dealloc.cta_group::1.sync.aligned.b32 %0, %1;" :: "r"(t), "r"((uint32_t)(n)))
#define TCGEN05_RELINQUISH()  asm volatile("tcgen05.relinquish_alloc_permit.cta_group::1.sync.aligned;")
#define TCGEN05_COMMIT(a)     asm volatile("tcgen05.commit.cta_group::1.mbarrier::arrive::one.shared::cluster.b64 [%0];" :: "r"((uint32_t)(a)) : "memory")
#define TCGEN05_FENCE_AFTER() asm volatile("tcgen05.fence::after_thread_sync;" ::: "memory")
#define TCGEN05_WAIT_LD()     asm volatile("tcgen05.wait::ld.sync.aligned;" ::: "memory")
#define TCGEN05_LD_X32(r, t) \
    asm volatile("tcgen05.ld.sync.aligned.32x32b.x32.b32 " \
        "{%0, %1, %2, %3, %4, %5, %6, %7, %8, %9, %10, %11, %12, %13, %14, %15, " \
        " %16, %17, %18, %19, %20, %21, %22, %23, %24, %25, %26, %27, %28, %29, %30, %31}, [%32];" \
        : "=r"((r)[0]), "=r"((r)[1]), "=r"((r)[2]), "=r"((r)[3]), "=r"((r)[4]), "=r"((r)[5]), "=r"((r)[6]), "=r"((r)[7]), \
          "=r"((r)[8]), "=r"((r)[9]), "=r"((r)[10]), "=r"((r)[11]), "=r"((r)[12]), "=r"((r)[13]), "=r"((r)[14]), "=r"((r)[15]), \
          "=r"((r)[16]), "=r"((r)[17]), "=r"((r)[18]), "=r"((r)[19]), "=r"((r)[20]), "=r"((r)[21]), "=r"((r)[22]), "=r"((r)[23]), \
          "=r"((r)[24]), "=r"((r)[25]), "=r"((r)[26]), "=r"((r)[27]), "=r"((r)[28]), "=r"((r)[29]), "=r"((r)[30]), "=r"((r)[31]) \
        : "r"(t))
__device__ __forceinline__ void mma_tf32_ss(uint32_t d, uint64_t ad, uint64_t bd, uint32_t idesc, bool en) {
    uint32_t e = en ? 1u : 0u;
    asm volatile("{\n\t.reg .pred p;\n\tsetp.ne.u32 p, %5, 0;\n\t"
        "tcgen05.mma.cta_group::1.kind::tf32 [%0], %1, %2, %3, {%4, %4, %4, %4}, p;\n\t}"
        :: "r"(d), "l"(ad), "l"(bd), "r"(idesc), "r"(0u), "r"(e) : "memory");
}
#endif

static constexpr uint64_t DESC_BASE =
    (uint64_t(2) << 61) | (uint64_t(1) << 46) | (uint64_t(64) << 32) | (uint64_t(1) << 16);
#define MK_DESC(a) (DESC_BASE | ((uint64_t)((a) >> 4) & 0x3FFF))
#define SWZ(o) ((o) ^ (((o) >> 3) & 0x70))

// ---------------- scratch (hi plane at 0, lo plane at +ROWS*K) ----------------
__device__ float g_silu[Bc * Mc];
__device__ float g_ada[Bc * ADA];
__device__ float g_ckr[Bc * Tc * Mc];
__device__ float g_cv [Bc * Tc * Mc];
__device__ float g_sk [Bc * Tc * Mc];
__device__ float g_sv [Bc * Tc * Mc];
__device__ float g_xt  [2 * ROWS * Mc];
__device__ float g_qkv [ROWS * M3];
__device__ float g_tout[2 * ROWS * Mc];
__device__ float g_proj[2 * ROWS * Mc];
__device__ float g_mod [2 * ROWS * Mc];
__device__ float g_satt[2 * ROWS * Mc];
__device__ float g_h   [2 * (size_t)ROWS * FFD];
__device__ float gw_tqkv[2 * M3 * Mc];
__device__ float gw_sqkv[2 * M3 * Mc];
__device__ float gw_tout[2 * Mc * Mc];
__device__ float gw_tfc [2 * Mc * Mc];
__device__ float gw_sout[2 * Mc * Mc];
__device__ float gw_w1  [2 * FFD * Mc];
__device__ float gw_w2  [2 * Mc * FFD];

// ---------------- small kernels ----------------
__global__ void silu_k(const float* __restrict__ c4t, float* __restrict__ out) {
    int i = blockIdx.x * 256 + threadIdx.x;
    if (i < Bc * Mc) { float v = c4t[i]; out[i] = v / (1.f + expf(-v)); }
}

__global__ void ada_k(const float* __restrict__ s, const float* __restrict__ W,
                      const float* __restrict__ bias, float* __restrict__ out) {
    int col = blockIdx.x * 256 + threadIdx.x;
    int b = blockIdx.y;
    const float* sp = s + b * Mc;
    float a0 = 0.f, a1 = 0.f, a2 = 0.f, a3 = 0.f;
    for (int k = 0; k < Mc; k += 4) {
        a0 = fmaf(sp[k + 0], __ldg(&W[(size_t)(k + 0) * ADA + col]), a0);
        a1 = fmaf(sp[k + 1], __ldg(&W[(size_t)(k + 1) * ADA + col]), a1);
        a2 = fmaf(sp[k + 2], __ldg(&W[(size_t)(k + 2) * ADA + col]), a2);
        a3 = fmaf(sp[k + 3], __ldg(&W[(size_t)(k + 3) * ADA + col]), a3);
    }
    out[(size_t)b * ADA + col] = (a0 + a1) + (a2 + a3) + bias[col];
}

__global__ void cproj4_k(const float* __restrict__ c,
                         const float* __restrict__ W0, const float* __restrict__ W1,
                         const float* __restrict__ W2, const float* __restrict__ W3,
                         float* __restrict__ o0, float* __restrict__ o1,
                         float* __restrict__ o2, float* __restrict__ o3) {
    int z = blockIdx.z;
    const float* W = (z == 0) ? W0 : (z == 1) ? W1 : (z == 2) ? W2 : W3;
    float* O = (z == 0) ? o0 : (z == 1) ? o1 : (z == 2) ? o2 : o3;
    int col = blockIdx.x * 128 + threadIdx.x;
    int r = blockIdx.y;
    const float* cp = c + (size_t)r * Mc;
    float a0 = 0.f, a1 = 0.f, a2 = 0.f, a3 = 0.f;
    for (int k = 0; k < Mc; k += 4) {
        a0 = fmaf(cp[k + 0], __ldg(&W[(size_t)(k + 0) * Mc + col]), a0);
        a1 = fmaf(cp[k + 1], __ldg(&W[(size_t)(k + 1) * Mc + col]), a1);
        a2 = fmaf(cp[k + 2], __ldg(&W[(size_t)(k + 2) * Mc + col]), a2);
        a3 = fmaf(cp[k + 3], __ldg(&W[(size_t)(k + 3) * Mc + col]), a3);
    }
    O[(size_t)r * Mc + col] = (a0 + a1) + (a2 + a3);
}

__global__ void rotc_k(float* __restrict__ ck, const int* __restrict__ f) {
    int r = blockIdx.x;
    int t = r & 15;
    float* p = ck + (size_t)r * Mc;
    float pos = (float)f[t];
    for (int idx = threadIdx.x; idx < Hc * 36; idx += 256) {
        int hh = idx / 36, i = idx - hh * 36;
        float inv = expf(-LN10000 * (float)(2 * i) * (1.f / 72.f));
        float ang = pos * inv;
        float cs = cosf(ang), sn = sinf(ang);
        int base = hh * 72 + 2 * i;
        float a = p[base], b = p[base + 1];
        p[base]     = a * cs - b * sn;
        p[base + 1] = b * cs + a * sn;
    }
}

// W[K,N] -> out[0][N][K] = hi (tf32-exact), out[1][N][K] = lo
__global__ __launch_bounds__(256)
void wsplit_k(const float* __restrict__ W, int K, int N, float* __restrict__ out) {
    __shared__ float tile[32][33];
    int n0 = blockIdx.x * 32, k0 = blockIdx.y * 32;
    int tx = threadIdx.x & 31, ty = threadIdx.x >> 5;
    for (int j = ty; j < 32; j += 8)
        tile[j][tx] = W[(size_t)(k0 + j) * N + n0 + tx];
    __syncthreads();
    float* hi = out;
    float* lo = out + (size_t)N * K;
    for (int j = ty; j < 32; j += 8) {
        float h, l;
        split2(tile[tx][j], h, l);
        size_t o = (size_t)(n0 + j) * K + k0 + tx;
        hi[o] = h;
        lo[o] = l;
    }
}

// LN(1e-5)*w+b, permuted to (B,N,T), split hi/lo output
__global__ __launch_bounds__(256)
void ln1_k(const float* __restrict__ x, const float* __restrict__ w,
           const float* __restrict__ bz, float* __restrict__ out) {
    __shared__ float row[Mc];
    __shared__ float red[256];
    int r = blockIdx.x, tid = threadIdx.x;
    const float* xp = x + (size_t)r * Mc;
    float s = 0.f;
    for (int c = tid; c < Mc; c += 256) { float v = xp[c]; row[c] = v; s += v; }
    red[tid] = s; __syncthreads();
    for (int o = 128; o > 0; o >>= 1) { if (tid < o) red[tid] += red[tid + o]; __syncthreads(); }
    float mu = red[0] * (1.f / Mc);
    __syncthreads();
    float s2 = 0.f;
    for (int c = tid; c < Mc; c += 256) { float d = row[c] - mu; s2 += d * d; }
    red[tid] = s2; __syncthreads();
    for (int o = 128; o > 0; o >>= 1) { if (tid < o) red[tid] += red[tid + o]; __syncthreads(); }
    float rstd = rsqrtf(red[0] * (1.f / Mc) + 1e-5f);
    int b = r >> 12, t = (r >> 8) & 15, n = r & 255;
    float* op = out + ((size_t)(((b << 8) + n) * 16 + t)) * Mc;
    for (int c = tid; c < Mc; c += 256) {
        float h, l;
        split2((row[c] - mu) * rstd * w[c] + bz[c], h, l);
        op[c] = h;
        op[c + (size_t)ROWS * Mc] = l;
    }
}

// LN(eps)*(1+sc)+sh, same row order, split hi/lo output
__global__ __launch_bounds__(256)
void lnmod_k(const float* __restrict__ in, const float* __restrict__ ada,
             int shOff, int scOff, float eps, float* __restrict__ out) {
    __shared__ float row[Mc];
    __shared__ float red[256];
    int r = blockIdx.x, tid = threadIdx.x;
    const float* xp = in + (size_t)r * Mc;
    float s = 0.f;
    for (int c = tid; c < Mc; c += 256) { float v = xp[c]; row[c] = v; s += v; }
    red[tid] = s; __syncthreads();
    for (int o = 128; o > 0; o >>= 1) { if (tid < o) red[tid] += red[tid + o]; __syncthreads(); }
    float mu = red[0] * (1.f / Mc);
    __syncthreads();
    float s2 = 0.f;
    for (int c = tid; c < Mc; c += 256) { float d = row[c] - mu; s2 += d * d; }
    red[tid] = s2; __syncthreads();
    for (int o = 128; o > 0; o >>= 1) { if (tid < o) red[tid] += red[tid + o]; __syncthreads(); }
    float rstd = rsqrtf(red[0] * (1.f / Mc) + eps);
    int b = r >> 12;
    const float* sh = ada + (size_t)b * ADA + shOff;
    const float* sc = ada + (size_t)b * ADA + scOff;
    float* op = out + (size_t)r * Mc;
    for (int c = tid; c < Mc; c += 256) {
        float h, l;
        split2((row[c] - mu) * rstd * (1.f + sc[c]) + sh[c], h, l);
        op[c] = h;
        op[c + (size_t)ROWS * Mc] = l;
    }
}

// ---------------- tcgen05 tf32x3 GEMM, 256x192 tile, cp.async pipeline ----------------
// A: pre-split activations (hi at A, lo at A+aPlane). Wsp = [hi;lo] [N][K].
// Stage: Ahi 0 (32K) Alo 32K Bhi 64K (24K) Blo 88K.
// EPI: 0 plain | 1 gelu(acc+bias) | 2 C += gate*(acc+bias) | 3 resid+acc+bias w/ A row permute
// SPL: 1 -> write split hi/lo planes (C, C+ROWS*Ncols)
#define STAGE 114688
#define GEMM_SMEM (1024 + 2 * STAGE)

#if HAS_TCGEN05
__device__ __forceinline__ void issue_mma_chunk(uint32_t tmem, uint32_t bb, bool first) {
    const uint32_t idesc = (1u << 4) | (2u << 7) | (2u << 10) | (24u << 17) | (8u << 24);
    uint64_t dA0h = MK_DESC(bb),         uint64_tdummy = 0;
    uint64_t dA1h = MK_DESC(bb + 16384);
    uint64_t dA0l = MK_DESC(bb + 32768), dA1l = MK_DESC(bb + 49152);
    uint64_t dBh  = MK_DESC(bb + 65536), dBl  = MK_DESC(bb + 90112);
    (void)uint64_tdummy;
#pragma unroll
    for (int k4 = 0; k4 < 4; k4++) {
        bool en = !(first && k4 == 0);
        mma_tf32_ss(tmem,       dA0h + 2 * k4, dBh + 2 * k4, idesc, en);
        mma_tf32_ss(tmem + 192, dA1h + 2 * k4, dBh + 2 * k4, idesc, en);
    }
#pragma unroll
    for (int k4 = 0; k4 < 4; k4++) {
        mma_tf32_ss(tmem,       dA0h + 2 * k4, dBl + 2 * k4, idesc, true);
        mma_tf32_ss(tmem + 192, dA1h + 2 * k4, dBl + 2 * k4, idesc, true);
        mma_tf32_ss(tmem,       dA0l + 2 * k4, dBh + 2 * k4, idesc, true);
        mma_tf32_ss(tmem + 192, dA1l + 2 * k4, dBh + 2 * k4, idesc, true);
    }
}
#endif

template<int EPI, int SPL>
__global__ __launch_bounds__(256)
void tc_gemm(const float* __restrict__ A, size_t aPlane, const float* __restrict__ Wsp,
             float* __restrict__ C, int Ncols, int Kdim,
             const float* __restrict__ bias, const float* __restrict__ resid,
             const float* __restrict__ gate) {
    extern __shared__ char smem[];
    int tid = threadIdx.x;
    const int row0 = blockIdx.y * 256, col0 = blockIdx.x * 192;
#if HAS_TCGEN05
    uint32_t sb = smem_u32(smem);
    int wid = tid >> 5, lane = tid & 31;
    const float* Bhi = Wsp;
    const float* Blo = Wsp + (size_t)Ncols * Kdim;

    if (tid == 0) { MBARRIER_INIT(sb + 16, 1); MBARRIER_INIT(sb + 32, 1); MBARRIER_INIT(sb + 48, 1); }
    if (wid == 0) TCGEN05_ALLOC(sb + 0, 512);
    __syncthreads();
    uint32_t tmem;
    asm volatile("ld.shared.b32 %0, [%1];" : "=r"(tmem) : "r"(sb));

    int nch = Kdim >> 5;
    for (int i = 0; i < nch; i++) {
        int p = i & 1;
        if (i >= 2) { MBARRIER_WAIT_PARITY(sb + 16 + p * 16, ((i >> 1) - 1) & 1); }
        uint32_t bufb = sb + 1024 + p * STAGE;
        int k0 = i << 5;
        // A: 2048 16B units (hi+lo)
#pragma unroll
        for (int it = 0; it < 8; it++) {
            int idx = it * 256 + tid;
            int r = idx >> 3, q = idx & 7;
            int gr = row0 + r;
            if (EPI == 3) { int bb = gr >> 12, tt = (gr >> 8) & 15, nn = gr & 255; gr = ((bb << 8) + nn) * 16 + tt; }
            const float* src = A + (size_t)gr * Kdim + k0 + q * 4;
            uint32_t off = SWZ((uint32_t)(r * 128 + q * 16));
            CP_ASYNC16(bufb + off, src);
            CP_ASYNC16(bufb + 32768 + off, src + aPlane);
        }
        // B: 1536 16B units (hi+lo)
#pragma unroll
        for (int it = 0; it < 6; it++) {
            int idx = it * 256 + tid;
            int n = idx >> 3, q = idx & 7;
            size_t gof = (size_t)(col0 + n) * Kdim + k0 + q * 4;
            uint32_t off = SWZ((uint32_t)(n * 128 + q * 16));
            CP_ASYNC16(bufb + 65536 + off, Bhi + gof);
            CP_ASYNC16(bufb + 90112 + off, Blo + gof);
        }
        CP_COMMIT();
        if (i >= 1) {
            CP_WAIT(1);
            __syncthreads();
            if (wid == 0 && elect1()) {
                asm volatile("fence.proxy.async.shared::cta;" ::: "memory");
                issue_mma_chunk(tmem, sb + 1024 + ((i - 1) & 1) * STAGE, (i - 1) == 0);
                TCGEN05_COMMIT(sb + 16 + ((i - 1) & 1) * 16);
            }
        }
    }
    CP_WAIT(0);
    __syncthreads();
    if (wid == 0 && elect1()) {
        asm volatile("fence.proxy.async.shared::cta;" ::: "memory");
        issue_mma_chunk(tmem, sb + 1024 + ((nch - 1) & 1) * STAGE, (nch - 1) == 0);
        TCGEN05_COMMIT(sb + 16 + ((nch - 1) & 1) * 16);
        TCGEN05_COMMIT(sb + 48);
    }
    MBARRIER_WAIT_PARITY(sb + 48, 0);
    TCGEN05_FENCE_AFTER();
    __syncthreads();

    // epilogue: 3 slabs of 64 cols; TMEM -> smem [256][65] -> float4 STG
    float* st = (float*)(smem + 1024);
    int half = wid >> 2, part = wid & 3;
#pragma unroll 1
    for (int s = 0; s < 3; s++) {
        int colb = s * 64;
        uint32_t regs[64];
        TCGEN05_LD_X32(regs, tmem + half * 192 + colb);
        TCGEN05_LD_X32(regs + 32, tmem + half * 192 + colb + 32);
        TCGEN05_WAIT_LD();
        int row = half * 128 + part * 32 + lane;
#pragma unroll
        for (int j = 0; j < 64; j++) st[row * 65 + j] = __uint_as_float(regs[j]);
        __syncthreads();
#pragma unroll 4
        for (int it = 0; it < 16; it++) {
            int idx = it * 256 + tid;
            int r = idx >> 4, q = idx & 15;
            int grow = row0 + r;
            int gcol = col0 + colb + q * 4;
            float v0 = st[r * 65 + q * 4 + 0];
            float v1 = st[r * 65 + q * 4 + 1];
            float v2 = st[r * 65 + q * 4 + 2];
            float v3 = st[r * 65 + q * 4 + 3];
            size_t o = (size_t)grow * Ncols + gcol;
            if (EPI == 0 && !SPL) {
                *(float4*)&C[o] = make_float4(v0, v1, v2, v3);
            } else if (EPI == 0 && SPL) {
                float4 hv, lv;
                split2(v0, hv.x, lv.x); split2(v1, hv.y, lv.y);
                split2(v2, hv.z, lv.z); split2(v3, hv.w, lv.w);
                *(float4*)&C[o] = hv;
                *(float4*)&C[o + (size_t)ROWS * Ncols] = lv;
            } else if (EPI == 1) {
                float vv[4] = {v0, v1, v2, v3};
                float4 hv, lv;
                float* hp = &hv.x; float* lp = &lv.x;
#pragma unroll
                for (int j = 0; j < 4; j++) {
                    float v = vv[j] + bias[gcol + j];
                    float u = 0.7978845608028654f * (v + 0.044715f * v * v * v);
                    float g = 0.5f * v * (1.f + tanhf(u));
                    split2(g, hp[j], lp[j]);
                }
                *(float4*)&C[o] = hv;
                if (SPL) *(float4*)&C[o + (size_t)ROWS * Ncols] = lv;
            } else if (EPI == 2) {
                int bI = grow >> 12;
                float4 cur = *(const float4*)&C[o];
                const float* gp = gate + (size_t)bI * ADA + gcol;
                float b0 = bias ? bias[gcol + 0] : 0.f;
                float b1 = bias ? bias[gcol + 1] : 0.f;
                float b2 = bias ? bias[gcol + 2] : 0.f;
                float b3 = bias ? bias[gcol + 3] : 0.f;
                cur.x += gp[0] * (v0 + b0);
                cur.y += gp[1] * (v1 + b1);
                cur.z += gp[2] * (v2 + b2);
                cur.w += gp[3] * (v3 + b3);
                *(float4*)&C[o] = cur;
            } else {
                float4 res = *(const float4*)&resid[o];
                res.x += v0 + bias[gcol + 0];
                res.y += v1 + bias[gcol + 1];
                res.z += v2 + bias[gcol + 2];
                res.w += v3 + bias[gcol + 3];
                *(float4*)&C[o] = res;
            }
        }
        __syncthreads();
    }
    if (wid == 0) { TCGEN05_RELINQUISH(); TCGEN05_DEALLOC(tmem, 512); }
#else
    // generic-arch compile-only fallback
    const float* Bhi = Wsp;
    const float* Blo = Wsp + (size_t)Ncols * Kdim;
    for (int e = tid; e < 256 * 192; e += 256) {
        int r = e / 192, cI = e % 192;
        int grow = row0 + r;
        int ar = grow;
        if (EPI == 3) { int bb = ar >> 12, tt = (ar >> 8) & 15, nn = ar & 255; ar = ((bb << 8) + nn) * 16 + tt; }
        int gcol = col0 + cI;
        float acc = 0.f;
        for (int k = 0; k < Kdim; k++)
            acc += (A[(size_t)ar * Kdim + k] + A[aPlane + (size_t)ar * Kdim + k]) *
                   (Bhi[(size_t)gcol * Kdim + k] + Blo[(size_t)gcol * Kdim + k]);
        size_t o = (size_t)grow * Ncols + gcol;
        if (EPI == 0 && !SPL) C[o] = acc;
        else if (EPI == 0 && SPL) { float h, l; split2(acc, h, l); C[o] = h; C[o + (size_t)ROWS * Ncols] = l; }
        else if (EPI == 1) {
            float v = acc + bias[gcol];
            float u = 0.7978845608028654f * (v + 0.044715f * v * v * v);
            float g = 0.5f * v * (1.f + tanhf(u));
            float h, l; split2(g, h, l);
            C[o] = h;
            if (SPL) C[o + (size_t)ROWS * Ncols] = l;
        } else if (EPI == 2) {
            int bI = grow >> 12;
            float bbv = bias ? bias[gcol] : 0.f;
            C[o] = C[o] + gate[(size_t)bI * ADA + gcol] * (acc + bbv);
        } else {
            C[o] = resid[o] + acc + bias[gcol];
        }
    }
#endif
}

// ---------------- temporal attention (split hi/lo output) ----------------
__global__ __launch_bounds__(512)
void tattn_k(const float* __restrict__ qkv, const float* __restrict__ ckr,
             const float* __restrict__ cv, const int* __restrict__ f,
             float* __restrict__ out) {
    __shared__ float Qs[16][72];
    __shared__ float Ks[32][73];
    __shared__ float Vs[32][73];
    __shared__ float Ps[16][32];
    int blk = blockIdx.x;
    int h = blk & 15;
    int bn = blk >> 4;
    int b = bn >> 8;
    int tid = threadIdx.x;
    for (int idx = tid; idx < 16 * 72; idx += 512) {
        int t = idx / 72, d = idx - t * 72;
        size_t base = ((size_t)(bn * 16 + t)) * M3 + h * 72 + d;
        Qs[t][d]      = qkv[base] * QK_SCALE;
        Ks[16 + t][d] = qkv[base + Mc];
        Vs[16 + t][d] = qkv[base + 2 * Mc];
        size_t cb = ((size_t)(b * 16 + t)) * Mc + h * 72 + d;
        Ks[t][d] = ckr[cb];
        Vs[t][d] = cv[cb];
    }
    __syncthreads();
    for (int idx = tid; idx < 16 * 36; idx += 512) {
        int t = idx / 36, i = idx - t * 36;
        float inv = expf(-LN10000 * (float)(2 * i) * (1.f / 72.f));
        float ang = (float)f[t] * inv;
        float cs = cosf(ang), sn = sinf(ang);
        float q0 = Qs[t][2 * i], q1 = Qs[t][2 * i + 1];
        Qs[t][2 * i]     = q0 * cs - q1 * sn;
        Qs[t][2 * i + 1] = q1 * cs + q0 * sn;
        float k0 = Ks[16 + t][2 * i], k1 = Ks[16 + t][2 * i + 1];
        Ks[16 + t][2 * i]     = k0 * cs - k1 * sn;
        Ks[16 + t][2 * i + 1] = k1 * cs + k0 * sn;
    }
    __syncthreads();
    int w = tid >> 5, lane = tid & 31;
    float a = 0.f;
#pragma unroll
    for (int d = 0; d < 72; d++) a += Qs[w][d] * Ks[lane][d];
    float mx = a;
    for (int o = 16; o > 0; o >>= 1) mx = fmaxf(mx, __shfl_xor_sync(0xffffffffu, mx, o));
    float e = expf(a - mx);
    float s = e;
    for (int o = 16; o > 0; o >>= 1) s += __shfl_xor_sync(0xffffffffu, s, o);
    Ps[w][lane] = e / s;
    __syncthreads();
    for (int idx = tid; idx < 16 * 72; idx += 512) {
        int t = idx / 72, d = idx - t * 72;
        float o = 0.f;
#pragma unroll
        for (int j = 0; j < 32; j++) o += Ps[t][j] * Vs[j][d];
        size_t oo = ((size_t)(bn * 16 + t)) * Mc + h * 72 + d;
        float hh, ll;
        split2(o, hh, ll);
        out[oo] = hh;
        out[oo + (size_t)ROWS * Mc] = ll;
    }
}

// ---------------- spatial attention (split hi/lo output) ----------------
__global__ __launch_bounds__(256)
void sattn_k(const float* __restrict__ qkv2, const float* __restrict__ sk,
             const float* __restrict__ sv, float* __restrict__ out) {
    __shared__ float Qs[32][72];
    __shared__ float L[32][257];
    int qt = blockIdx.x;
    int bth = blockIdx.y;
    int h = bth & 15, bt = bth >> 4;
    int tid = threadIdx.x;
    for (int idx = tid; idx < 32 * 72; idx += 256) {
        int q = idx / 72, d = idx - q * 72;
        int n = qt * 32 + q;
        Qs[q][d] = qkv2[((size_t)(bt * 256 + n)) * M3 + h * 72 + d] * QK_SCALE;
    }
    __syncthreads();
    int q = tid >> 3, g = tid & 7;
    for (int j = g; j < 257; j += 8) {
        const float* kp = (j == 0)
            ? (sk + (size_t)bt * Mc + h * 72)
            : (qkv2 + ((size_t)(bt * 256 + (j - 1))) * M3 + Mc + h * 72);
        float a = 0.f;
#pragma unroll
        for (int d = 0; d < 72; d++) a += Qs[q][d] * kp[d];
        L[q][j] = a;
    }
    float mx = -1e30f;
    for (int j = g; j < 257; j += 8) mx = fmaxf(mx, L[q][j]);
    for (int o = 4; o > 0; o >>= 1) mx = fmaxf(mx, __shfl_xor_sync(0xffffffffu, mx, o));
    float s = 0.f;
    for (int j = g; j < 257; j += 8) { float e = expf(L[q][j] - mx); L[q][j] = e; s += e; }
    for (int o = 4; o > 0; o >>= 1) s += __shfl_xor_sync(0xffffffffu, s, o);
    float invs = 1.f / s;
    __syncwarp();
    int d0 = g * 9;
    float o9[9];
#pragma unroll
    for (int i = 0; i < 9; i++) o9[i] = 0.f;
    for (int j = 0; j < 257; j++) {
        float p = L[q][j] * invs;
        const float* vp = (j == 0)
            ? (sv + (size_t)bt * Mc + h * 72 + d0)
            : (qkv2 + ((size_t)(bt * 256 + (j - 1))) * M3 + 2 * Mc + h * 72 + d0);
#pragma unroll
        for (int i = 0; i < 9; i++) o9[i] += p * vp[i];
    }
    int n = qt * 32 + q;
    size_t ob = ((size_t)(bt * 256 + n)) * Mc + h * 72 + d0;
#pragma unroll
    for (int i = 0; i < 9; i++) {
        float hh, ll;
        split2(o9[i], hh, ll);
        out[ob + i] = hh;
        out[ob + i + (size_t)ROWS * Mc] = ll;
    }
}

// ---------------- launch ----------------
extern "C" void kernel_launch(void* const* d_in, const int* in_sizes, int n_in,
                              void* d_out, int out_size) {
    const float* x      = (const float*)d_in[0];
    const float* c4t    = (const float*)d_in[1];
    const float* c      = (const float*)d_in[2];
    const float* W_ada  = (const float*)d_in[3];
    const float* b_ada  = (const float*)d_in[4];
    const float* tn_w   = (const float*)d_in[5];
    const float* tn_b   = (const float*)d_in[6];
    const float* t_qkv  = (const float*)d_in[7];
    const float* t_k    = (const float*)d_in[8];
    const float* t_v    = (const float*)d_in[9];
    const float* t_out  = (const float*)d_in[10];
    const float* t_fc_w = (const float*)d_in[11];
    const float* t_fc_b = (const float*)d_in[12];
    const float* s_qkv  = (const float*)d_in[13];
    const float* s_k    = (const float*)d_in[14];
    const float* s_v    = (const float*)d_in[15];
    const float* s_out  = (const float*)d_in[16];
    const float* mlp_w1 = (const float*)d_in[17];
    const float* mlp_b1 = (const float*)d_in[18];
    const float* mlp_w2 = (const float*)d_in[19];
    const float* mlp_b2 = (const float*)d_in[20];
    const int*   f      = (const int*)d_in[21];
    float* out = (float*)d_out;

    float *p_silu, *p_ada, *p_ckr, *p_cv, *p_sk, *p_sv;
    float *p_xt, *p_qkv, *p_tout, *p_proj, *p_mod, *p_satt, *p_h;
    float *w_tqkv, *w_sqkv, *w_tout, *w_tfc, *w_sout, *w_w1, *w_w2;
    cudaGetSymbolAddress((void**)&p_silu, g_silu);
    cudaGetSymbolAddress((void**)&p_ada,  g_ada);
    cudaGetSymbolAddress((void**)&p_ckr,  g_ckr);
    cudaGetSymbolAddress((void**)&p_cv,   g_cv);
    cudaGetSymbolAddress((void**)&p_sk,   g_sk);
    cudaGetSymbolAddress((void**)&p_sv,   g_sv);
    cudaGetSymbolAddress((void**)&p_xt,   g_xt);
    cudaGetSymbolAddress((void**)&p_qkv,  g_qkv);
    cudaGetSymbolAddress((void**)&p_tout, g_tout);
    cudaGetSymbolAddress((void**)&p_proj, g_proj);
    cudaGetSymbolAddress((void**)&p_mod,  g_mod);
    cudaGetSymbolAddress((void**)&p_satt, g_satt);
    cudaGetSymbolAddress((void**)&p_h,    g_h);
    cudaGetSymbolAddress((void**)&w_tqkv, gw_tqkv);
    cudaGetSymbolAddress((void**)&w_sqkv, gw_sqkv);
    cudaGetSymbolAddress((void**)&w_tout, gw_tout);
    cudaGetSymbolAddress((void**)&w_tfc,  gw_tfc);
    cudaGetSymbolAddress((void**)&w_sout, gw_sout);
    cudaGetSymbolAddress((void**)&w_w1,   gw_w1);
    cudaGetSymbolAddress((void**)&w_w2,   gw_w2);

    cudaFuncSetAttribute(tc_gemm<0,0>, cudaFuncAttributeMaxDynamicSharedMemorySize, GEMM_SMEM);
    cudaFuncSetAttribute(tc_gemm<0,1>, cudaFuncAttributeMaxDynamicSharedMemorySize, GEMM_SMEM);
    cudaFuncSetAttribute(tc_gemm<1,1>, cudaFuncAttributeMaxDynamicSharedMemorySize, GEMM_SMEM);
    cudaFuncSetAttribute(tc_gemm<2,0>, cudaFuncAttributeMaxDynamicSharedMemorySize, GEMM_SMEM);
    cudaFuncSetAttribute(tc_gemm<3,0>, cudaFuncAttributeMaxDynamicSharedMemorySize, GEMM_SMEM);

    const size_t plM = (size_t)ROWS * Mc;
    const size_t plF = (size_t)ROWS * FFD;

    // weight preprocessing
    wsplit_k<<<dim3(M3 / 32, Mc / 32), 256>>>(t_qkv, Mc, M3, w_tqkv);
    wsplit_k<<<dim3(M3 / 32, Mc / 32), 256>>>(s_qkv, Mc, M3, w_sqkv);
    wsplit_k<<<dim3(Mc / 32, Mc / 32), 256>>>(t_out, Mc, Mc, w_tout);
    wsplit_k<<<dim3(Mc / 32, Mc / 32), 256>>>(t_fc_w, Mc, Mc, w_tfc);
    wsplit_k<<<dim3(Mc / 32, Mc / 32), 256>>>(s_out, Mc, Mc, w_sout);
    wsplit_k<<<dim3(FFD / 32, Mc / 32), 256>>>(mlp_w1, Mc, FFD, w_w1);
    wsplit_k<<<dim3(Mc / 32, FFD / 32), 256>>>(mlp_w2, FFD, Mc, w_w2);

    // adaLN + conditioning
    silu_k<<<9, 256>>>(c4t, p_silu);
    ada_k<<<dim3(27, 2), 256>>>(p_silu, W_ada, b_ada, p_ada);
    cproj4_k<<<dim3(9, 32, 4), 128>>>(c, t_k, t_v, s_k, s_v, p_ckr, p_cv, p_sk, p_sv);
    rotc_k<<<32, 256>>>(p_ckr, f);
    // temporal branch
    ln1_k<<<ROWS, 256>>>(x, tn_w, tn_b, p_xt);
    tc_gemm<0,0><<<dim3(18, 32), 256, GEMM_SMEM>>>(p_xt, plM, w_tqkv, p_qkv, M3, Mc, nullptr, nullptr, nullptr);
    tattn_k<<<ROWS, 512>>>(p_qkv, p_ckr, p_cv, f, p_tout);
    tc_gemm<0,1><<<dim3(6, 32), 256, GEMM_SMEM>>>(p_tout, plM, w_tout, p_proj, Mc, Mc, nullptr, nullptr, nullptr);
    tc_gemm<3,0><<<dim3(6, 32), 256, GEMM_SMEM>>>(p_proj, plM, w_tfc, out, Mc, Mc, t_fc_b, x, nullptr);
    // spatial branch
    lnmod_k<<<ROWS, 256>>>(out, p_ada, 0, Mc, 1e-6f, p_mod);
    tc_gemm<0,0><<<dim3(18, 32), 256, GEMM_SMEM>>>(p_mod, plM, w_sqkv, p_qkv, M3, Mc, nullptr, nullptr, nullptr);
    sattn_k<<<dim3(8, 512), 256>>>(p_qkv, p_sk, p_sv, p_satt);
    tc_gemm<2,0><<<dim3(6, 32), 256, GEMM_SMEM>>>(p_satt, plM, w_sout, out, Mc, Mc, nullptr, nullptr, p_ada + 2 * Mc);
    // MLP
    lnmod_k<<<ROWS, 256>>>(out, p_ada, 3 * Mc, 4 * Mc, 1e-6f, p_mod);
    tc_gemm<1,1><<<dim3(24, 32), 256, GEMM_SMEM>>>(p_mod, plM, w_w1, p_h, FFD, Mc, mlp_b1, nullptr, nullptr);
    tc_gemm<2,0><<<dim3(6, 32), 256, GEMM_SMEM>>>(p_h, plF, w_w2, out, Mc, FFD, mlp_b2, nullptr, p_ada + 5 * Mc);
}

// round 16
// speedup vs baseline: 2.7011x; 1.2153x over previous
#include <cuda_runtime.h>
#include <cuda_fp16.h>
#include <math.h>
#include <stdint.h>

#define Bc 2
#define Tc 16
#define Nc 256
#define Mc 1152
#define Hc 16
#define ROWS 8192
#define M3 3456
#define FFD 4608
#define ADA 6912
#define QK_SCALE 0.11785113019775793f
#define LN10000 9.210340371976184f

#if defined(__CUDA_ARCH_FEAT_SM103_ALL) || defined(__CUDA_ARCH_FEAT_SM100_ALL) || defined(__CUDA_ARCH_FEAT_SM101_ALL)
#define HAS_TCGEN05 1
#else
#define HAS_TCGEN05 0
#endif

__device__ __forceinline__ uint32_t smem_u32(const void* p) {
    uint32_t a;
    asm("{ .reg .u64 t; cvta.to.shared.u64 t, %1; cvt.u32.u64 %0, t; }" : "=r"(a) : "l"(p));
    return a;
}
__device__ __forceinline__ uint32_t elect1() {
    uint32_t p;
    asm volatile("{\n\t.reg .pred p;\n\telect.sync _|p, 0xFFFFFFFF;\n\tselp.b32 %0, 1, 0, p;\n\t}" : "=r"(p));
    return p;
}
__device__ __forceinline__ void split2h(float v, __half& h, __half& l) {
    h = __float2half_rn(v);
    l = __float2half_rn(v - __half2float(h));
}
#define MBARRIER_INIT(addr, count) \
    asm volatile("mbarrier.init.shared.b64 [%0], %1;" :: "r"((uint32_t)(addr)), "r"((uint32_t)(count)) : "memory")
#define MBARRIER_WAIT_PARITY(a, ph) do { \
    uint32_t _m = (uint32_t)(a), _p = (uint32_t)(ph), _d; \
    asm volatile("{\n\t.reg .pred p;\n\tmbarrier.try_wait.parity.acquire.cta.shared::cta.b64 p, [%1], %2;\n\tselp.b32 %0, 1, 0, p;\n\t}" : "=r"(_d) : "r"(_m), "r"(_p) : "memory"); \
    if (!_d) { \
        asm volatile("{\n\t.reg .pred P1;\n\tWL_%=:\n\tmbarrier.try_wait.parity.acquire.cta.shared::cta.b64 P1, [%0], %1, 0x989680;\n\t@P1 bra.uni WD_%=;\n\tbra.uni WL_%=;\n\tWD_%=:\n\t}" :: "r"(_m), "r"(_p) : "memory"); \
    } \
} while(0)
#define CP_ASYNC16(dst, src) \
    asm volatile("cp.async.cg.shared.global [%0], [%1], 16;" :: "r"((uint32_t)(dst)), "l"(src) : "memory")
#define CP_COMMIT() asm volatile("cp.async.commit_group;" ::: "memory")
#define CP_WAIT(n)  asm volatile("cp.async.wait_group %0;" :: "n"(n) : "memory")

#if HAS_TCGEN05
#define TCGEN05_ALLOC(a, n)   asm volatile("tcgen05.alloc.cta_group::1.sync.aligned.shared::cta.b32 [%0], %1;" :: "r"((uint32_t)(a)), "r"((uint32_t)(n)) : "memory")
#define TCGEN05_DEALLOC(t, n) asm volatile("tcgen05.dealloc.cta_group::1.sync.aligned.b32 %0, %1;" :: "r"(t), "r"((uint32_t)(n)))
#define TCGEN05_RELINQUISH()  asm volatile("tcgen05.relinquish_alloc_permit.cta_group::1.sync.aligned;")
#define TCGEN05_COMMIT(a)     asm volatile("tcgen05.commit.cta_group::1.mbarrier::arrive::one.shared::cluster.b64 [%0];" :: "r"((uint32_t)(a)) : "memory")
#define TCGEN05_FENCE_AFTER() asm volatile("tcgen05.fence::after_thread_sync;" ::: "memory")
#define TCGEN05_WAIT_LD()     asm volatile("tcgen05.wait::ld.sync.aligned;" ::: "memory")
#define TCGEN05_LD_X32(r, t) \
    asm volatile("tcgen05.ld.sync.aligned.32x32b.x32.b32 " \
        "{%0, %1, %2, %3, %4, %5, %6, %7, %8, %9, %10, %11, %12, %13, %14, %15, " \
        " %16, %17, %18, %19, %20, %21, %22, %23, %24, %25, %26, %27, %28, %29, %30, %31}, [%32];" \
        : "=r"((r)[0]), "=r"((r)[1]), "=r"((r)[2]), "=r"((r)[3]), "=r"((r)[4]), "=r"((r)[5]), "=r"((r)[6]), "=r"((r)[7]), \
          "=r"((r)[8]), "=r"((r)[9]), "=r"((r)[10]), "=r"((r)[11]), "=r"((r)[12]), "=r"((r)[13]), "=r"((r)[14]), "=r"((r)[15]), \
          "=r"((r)[16]), "=r"((r)[17]), "=r"((r)[18]), "=r"((r)[19]), "=r"((r)[20]), "=r"((r)[21]), "=r"((r)[22]), "=r"((r)[23]), \
          "=r"((r)[24]), "=r"((r)[25]), "=r"((r)[26]), "=r"((r)[27]), "=r"((r)[28]), "=r"((r)[29]), "=r"((r)[30]), "=r"((r)[31]) \
        : "r"(t))
__device__ __forceinline__ void mma_f16_ss(uint32_t d, uint64_t ad, uint64_t bd, uint32_t idesc, bool en) {
    uint32_t e = en ? 1u : 0u;
    asm volatile("{\n\t.reg .pred p;\n\tsetp.ne.u32 p, %5, 0;\n\t"
        "tcgen05.mma.cta_group::1.kind::f16 [%0], %1, %2, %3, {%4, %4, %4, %4}, p;\n\t}"
        :: "r"(d), "l"(ad), "l"(bd), "r"(idesc), "r"(0u), "r"(e) : "memory");
}
#endif

static constexpr uint64_t DESC_BASE =
    (uint64_t(2) << 61) | (uint64_t(1) << 46) | (uint64_t(64) << 32) | (uint64_t(1) << 16);
#define MK_DESC(a) (DESC_BASE | ((uint64_t)((a) >> 4) & 0x3FFF))
#define SWZ(o) ((o) ^ (((o) >> 3) & 0x70))

// ---------------- scratch (fp16 hi plane at 0, lo plane at +ROWS*K) ----------------
__device__ float g_silu[Bc * Mc];
__device__ float g_ada[Bc * ADA];
__device__ float g_ckr[Bc * Tc * Mc];
__device__ float g_cv [Bc * Tc * Mc];
__device__ float g_sk [Bc * Tc * Mc];
__device__ float g_sv [Bc * Tc * Mc];
__device__ __half g_xt  [2 * ROWS * Mc];
__device__ float  g_qkv [ROWS * M3];
__device__ __half g_tout[2 * ROWS * Mc];
__device__ __half g_proj[2 * ROWS * Mc];
__device__ __half g_mod [2 * ROWS * Mc];
__device__ __half g_satt[2 * ROWS * Mc];
__device__ __half g_h   [2 * (size_t)ROWS * FFD];
__device__ __half gw_tqkv[2 * M3 * Mc];
__device__ __half gw_sqkv[2 * M3 * Mc];
__device__ __half gw_tout[2 * Mc * Mc];
__device__ __half gw_tfc [2 * Mc * Mc];
__device__ __half gw_sout[2 * Mc * Mc];
__device__ __half gw_w1  [2 * FFD * Mc];
__device__ __half gw_w2  [2 * Mc * FFD];

// ---------------- small kernels ----------------
__global__ void silu_k(const float* __restrict__ c4t, float* __restrict__ out) {
    int i = blockIdx.x * 256 + threadIdx.x;
    if (i < Bc * Mc) { float v = c4t[i]; out[i] = v / (1.f + expf(-v)); }
}

__global__ void ada_k(const float* __restrict__ s, const float* __restrict__ W,
                      const float* __restrict__ bias, float* __restrict__ out) {
    int col = blockIdx.x * 256 + threadIdx.x;
    int b = blockIdx.y;
    const float* sp = s + b * Mc;
    float a0 = 0.f, a1 = 0.f, a2 = 0.f, a3 = 0.f;
    for (int k = 0; k < Mc; k += 4) {
        a0 = fmaf(sp[k + 0], __ldg(&W[(size_t)(k + 0) * ADA + col]), a0);
        a1 = fmaf(sp[k + 1], __ldg(&W[(size_t)(k + 1) * ADA + col]), a1);
        a2 = fmaf(sp[k + 2], __ldg(&W[(size_t)(k + 2) * ADA + col]), a2);
        a3 = fmaf(sp[k + 3], __ldg(&W[(size_t)(k + 3) * ADA + col]), a3);
    }
    out[(size_t)b * ADA + col] = (a0 + a1) + (a2 + a3) + bias[col];
}

__global__ void cproj4_k(const float* __restrict__ c,
                         const float* __restrict__ W0, const float* __restrict__ W1,
                         const float* __restrict__ W2, const float* __restrict__ W3,
                         float* __restrict__ o0, float* __restrict__ o1,
                         float* __restrict__ o2, float* __restrict__ o3) {
    int z = blockIdx.z;
    const float* W = (z == 0) ? W0 : (z == 1) ? W1 : (z == 2) ? W2 : W3;
    float* O = (z == 0) ? o0 : (z == 1) ? o1 : (z == 2) ? o2 : o3;
    int col = blockIdx.x * 128 + threadIdx.x;
    int r = blockIdx.y;
    const float* cp = c + (size_t)r * Mc;
    float a0 = 0.f, a1 = 0.f, a2 = 0.f, a3 = 0.f;
    for (int k = 0; k < Mc; k += 4) {
        a0 = fmaf(cp[k + 0], __ldg(&W[(size_t)(k + 0) * Mc + col]), a0);
        a1 = fmaf(cp[k + 1], __ldg(&W[(size_t)(k + 1) * Mc + col]), a1);
        a2 = fmaf(cp[k + 2], __ldg(&W[(size_t)(k + 2) * Mc + col]), a2);
        a3 = fmaf(cp[k + 3], __ldg(&W[(size_t)(k + 3) * Mc + col]), a3);
    }
    O[(size_t)r * Mc + col] = (a0 + a1) + (a2 + a3);
}

__global__ void rotc_k(float* __restrict__ ck, const int* __restrict__ f) {
    int r = blockIdx.x;
    int t = r & 15;
    float* p = ck + (size_t)r * Mc;
    float pos = (float)f[t];
    for (int idx = threadIdx.x; idx < Hc * 36; idx += 256) {
        int hh = idx / 36, i = idx - hh * 36;
        float inv = expf(-LN10000 * (float)(2 * i) * (1.f / 72.f));
        float ang = pos * inv;
        float cs = cosf(ang), sn = sinf(ang);
        int base = hh * 72 + 2 * i;
        float a = p[base], b = p[base + 1];
        p[base]     = a * cs - b * sn;
        p[base + 1] = b * cs + a * sn;
    }
}

// W[K,N] -> out[0][N][K] = fp16 hi, out[1][N][K] = fp16 lo
__global__ __launch_bounds__(256)
void wsplit_k(const float* __restrict__ W, int K, int N, __half* __restrict__ out) {
    __shared__ float tile[32][33];
    int n0 = blockIdx.x * 32, k0 = blockIdx.y * 32;
    int tx = threadIdx.x & 31, ty = threadIdx.x >> 5;
    for (int j = ty; j < 32; j += 8)
        tile[j][tx] = W[(size_t)(k0 + j) * N + n0 + tx];
    __syncthreads();
    __half* hi = out;
    __half* lo = out + (size_t)N * K;
    for (int j = ty; j < 32; j += 8) {
        __half h, l;
        split2h(tile[tx][j], h, l);
        size_t o = (size_t)(n0 + j) * K + k0 + tx;
        hi[o] = h;
        lo[o] = l;
    }
}

// LN(1e-5)*w+b, permuted to (B,N,T), fp16 hi/lo output
__global__ __launch_bounds__(256)
void ln1_k(const float* __restrict__ x, const float* __restrict__ w,
           const float* __restrict__ bz, __half* __restrict__ out) {
    __shared__ float row[Mc];
    __shared__ float red[256];
    int r = blockIdx.x, tid = threadIdx.x;
    const float* xp = x + (size_t)r * Mc;
    float s = 0.f;
    for (int c = tid; c < Mc; c += 256) { float v = xp[c]; row[c] = v; s += v; }
    red[tid] = s; __syncthreads();
    for (int o = 128; o > 0; o >>= 1) { if (tid < o) red[tid] += red[tid + o]; __syncthreads(); }
    float mu = red[0] * (1.f / Mc);
    __syncthreads();
    float s2 = 0.f;
    for (int c = tid; c < Mc; c += 256) { float d = row[c] - mu; s2 += d * d; }
    red[tid] = s2; __syncthreads();
    for (int o = 128; o > 0; o >>= 1) { if (tid < o) red[tid] += red[tid + o]; __syncthreads(); }
    float rstd = rsqrtf(red[0] * (1.f / Mc) + 1e-5f);
    int b = r >> 12, t = (r >> 8) & 15, n = r & 255;
    __half* op = out + ((size_t)(((b << 8) + n) * 16 + t)) * Mc;
    for (int c = tid; c < Mc; c += 256) {
        __half h, l;
        split2h((row[c] - mu) * rstd * w[c] + bz[c], h, l);
        op[c] = h;
        op[c + (size_t)ROWS * Mc] = l;
    }
}

// LN(eps)*(1+sc)+sh, fp16 hi/lo output
__global__ __launch_bounds__(256)
void lnmod_k(const float* __restrict__ in, const float* __restrict__ ada,
             int shOff, int scOff, float eps, __half* __restrict__ out) {
    __shared__ float row[Mc];
    __shared__ float red[256];
    int r = blockIdx.x, tid = threadIdx.x;
    const float* xp = in + (size_t)r * Mc;
    float s = 0.f;
    for (int c = tid; c < Mc; c += 256) { float v = xp[c]; row[c] = v; s += v; }
    red[tid] = s; __syncthreads();
    for (int o = 128; o > 0; o >>= 1) { if (tid < o) red[tid] += red[tid + o]; __syncthreads(); }
    float mu = red[0] * (1.f / Mc);
    __syncthreads();
    float s2 = 0.f;
    for (int c = tid; c < Mc; c += 256) { float d = row[c] - mu; s2 += d * d; }
    red[tid] = s2; __syncthreads();
    for (int o = 128; o > 0; o >>= 1) { if (tid < o) red[tid] += red[tid + o]; __syncthreads(); }
    float rstd = rsqrtf(red[0] * (1.f / Mc) + eps);
    int b = r >> 12;
    const float* sh = ada + (size_t)b * ADA + shOff;
    const float* sc = ada + (size_t)b * ADA + scOff;
    __half* op = out + (size_t)r * Mc;
    for (int c = tid; c < Mc; c += 256) {
        __half h, l;
        split2h((row[c] - mu) * rstd * (1.f + sc[c]) + sh[c], h, l);
        op[c] = h;
        op[c + (size_t)ROWS * Mc] = l;
    }
}

// ---------------- tcgen05 fp16x3 GEMM, 256x192 tile, TK=64, cp.async pipeline ----------------
// A: fp16 hi/lo planes (hi at A, lo at A+aPlane). Wsp = [hi;lo] [N][K] fp16.
// Stage bytes: Ahi 0 (32K) Alo 32768 Bhi 65536 (24K) Blo 90112.
// EPI: 0 plain | 1 gelu | 2 C += gate*(acc+bias) | 3 resid+acc+bias w/ A row permute
// SPL: 1 -> write fp16 hi/lo planes to Csp instead of C
#define STAGE 114688
#define GEMM_SMEM (1024 + 2 * STAGE)

#if HAS_TCGEN05
__device__ __forceinline__ void issue_mma_chunk(uint32_t tmem, uint32_t bb, bool first) {
    const uint32_t idesc = (1u << 4) | (24u << 17) | (8u << 24);  // f32 acc, fp16 a/b, N=192, M=128
    uint64_t dA0h = MK_DESC(bb);
    uint64_t dA1h = MK_DESC(bb + 16384);
    uint64_t dA0l = MK_DESC(bb + 32768), dA1l = MK_DESC(bb + 49152);
    uint64_t dBh  = MK_DESC(bb + 65536), dBl  = MK_DESC(bb + 90112);
#pragma unroll
    for (int k4 = 0; k4 < 4; k4++) {
        bool en = !(first && k4 == 0);
        mma_f16_ss(tmem,       dA0h + 2 * k4, dBh + 2 * k4, idesc, en);
        mma_f16_ss(tmem + 192, dA1h + 2 * k4, dBh + 2 * k4, idesc, en);
    }
#pragma unroll
    for (int k4 = 0; k4 < 4; k4++) {
        mma_f16_ss(tmem,       dA0h + 2 * k4, dBl + 2 * k4, idesc, true);
        mma_f16_ss(tmem + 192, dA1h + 2 * k4, dBl + 2 * k4, idesc, true);
        mma_f16_ss(tmem,       dA0l + 2 * k4, dBh + 2 * k4, idesc, true);
        mma_f16_ss(tmem + 192, dA1l + 2 * k4, dBh + 2 * k4, idesc, true);
    }
}
#endif

template<int EPI, int SPL>
__global__ __launch_bounds__(256)
void tc_gemm(const __half* __restrict__ A, size_t aPlane, const __half* __restrict__ Wsp,
             float* __restrict__ C, __half* __restrict__ Csp, int Ncols, int Kdim,
             const float* __restrict__ bias, const float* __restrict__ resid,
             const float* __restrict__ gate) {
    extern __shared__ char smem[];
    int tid = threadIdx.x;
    const int row0 = blockIdx.y * 256, col0 = blockIdx.x * 192;
#if HAS_TCGEN05
    uint32_t sb = smem_u32(smem);
    int wid = tid >> 5, lane = tid & 31;
    const __half* Bhi = Wsp;
    const __half* Blo = Wsp + (size_t)Ncols * Kdim;

    if (tid == 0) { MBARRIER_INIT(sb + 16, 1); MBARRIER_INIT(sb + 32, 1); MBARRIER_INIT(sb + 48, 1); }
    if (wid == 0) TCGEN05_ALLOC(sb + 0, 512);
    __syncthreads();
    uint32_t tmem;
    asm volatile("ld.shared.b32 %0, [%1];" : "=r"(tmem) : "r"(sb));

    int nch = Kdim >> 6;   // TK = 64
    for (int i = 0; i < nch; i++) {
        int p = i & 1;
        if (i >= 2) { MBARRIER_WAIT_PARITY(sb + 16 + p * 16, ((i >> 1) - 1) & 1); }
        uint32_t bufb = sb + 1024 + p * STAGE;
        int k0 = i << 6;
        // A: 256 rows x 64 K fp16 = 2048 16B units per plane
#pragma unroll
        for (int it = 0; it < 8; it++) {
            int idx = it * 256 + tid;
            int r = idx >> 3, q = idx & 7;
            int gr = row0 + r;
            if (EPI == 3) { int bb = gr >> 12, tt = (gr >> 8) & 15, nn = gr & 255; gr = ((bb << 8) + nn) * 16 + tt; }
            const __half* src = A + (size_t)gr * Kdim + k0 + q * 8;
            uint32_t off = SWZ((uint32_t)(r * 128 + q * 16));
            CP_ASYNC16(bufb + off, src);
            CP_ASYNC16(bufb + 32768 + off, src + aPlane);
        }
        // B: 192 rows x 64 K fp16 = 1536 16B units per plane
#pragma unroll
        for (int it = 0; it < 6; it++) {
            int idx = it * 256 + tid;
            int n = idx >> 3, q = idx & 7;
            size_t gof = (size_t)(col0 + n) * Kdim + k0 + q * 8;
            uint32_t off = SWZ((uint32_t)(n * 128 + q * 16));
            CP_ASYNC16(bufb + 65536 + off, Bhi + gof);
            CP_ASYNC16(bufb + 90112 + off, Blo + gof);
        }
        CP_COMMIT();
        if (i >= 1) {
            CP_WAIT(1);
            __syncthreads();
            if (wid == 0 && elect1()) {
                asm volatile("fence.proxy.async.shared::cta;" ::: "memory");
                issue_mma_chunk(tmem, sb + 1024 + ((i - 1) & 1) * STAGE, (i - 1) == 0);
                TCGEN05_COMMIT(sb + 16 + ((i - 1) & 1) * 16);
            }
        }
    }
    CP_WAIT(0);
    __syncthreads();
    if (wid == 0 && elect1()) {
        asm volatile("fence.proxy.async.shared::cta;" ::: "memory");
        issue_mma_chunk(tmem, sb + 1024 + ((nch - 1) & 1) * STAGE, (nch - 1) == 0);
        TCGEN05_COMMIT(sb + 16 + ((nch - 1) & 1) * 16);
        TCGEN05_COMMIT(sb + 48);
    }
    MBARRIER_WAIT_PARITY(sb + 48, 0);
    TCGEN05_FENCE_AFTER();
    __syncthreads();

    // epilogue: 3 slabs of 64 cols; TMEM -> smem [256][65] -> stores
    float* st = (float*)(smem + 1024);
    int half_ = wid >> 2, part = wid & 3;
#pragma unroll 1
    for (int s = 0; s < 3; s++) {
        int colb = s * 64;
        uint32_t regs[64];
        TCGEN05_LD_X32(regs, tmem + half_ * 192 + colb);
        TCGEN05_LD_X32(regs + 32, tmem + half_ * 192 + colb + 32);
        TCGEN05_WAIT_LD();
        int row = half_ * 128 + part * 32 + lane;
#pragma unroll
        for (int j = 0; j < 64; j++) st[row * 65 + j] = __uint_as_float(regs[j]);
        __syncthreads();
#pragma unroll 4
        for (int it = 0; it < 16; it++) {
            int idx = it * 256 + tid;
            int r = idx >> 4, q = idx & 15;
            int grow = row0 + r;
            int gcol = col0 + colb + q * 4;
            float v0 = st[r * 65 + q * 4 + 0];
            float v1 = st[r * 65 + q * 4 + 1];
            float v2 = st[r * 65 + q * 4 + 2];
            float v3 = st[r * 65 + q * 4 + 3];
            size_t o = (size_t)grow * Ncols + gcol;
            if (EPI == 0 && !SPL) {
                *(float4*)&C[o] = make_float4(v0, v1, v2, v3);
            } else if (EPI == 0 && SPL) {
                __half h0, l0, h1, l1, h2, l2, h3, l3;
                split2h(v0, h0, l0); split2h(v1, h1, l1);
                split2h(v2, h2, l2); split2h(v3, h3, l3);
                *(__half2*)&Csp[o]     = __halves2half2(h0, h1);
                *(__half2*)&Csp[o + 2] = __halves2half2(h2, h3);
                size_t o2 = o + (size_t)ROWS * Ncols;
                *(__half2*)&Csp[o2]     = __halves2half2(l0, l1);
                *(__half2*)&Csp[o2 + 2] = __halves2half2(l2, l3);
            } else if (EPI == 1) {
                float vv[4] = {v0, v1, v2, v3};
                __half hh[4], ll[4];
#pragma unroll
                for (int j = 0; j < 4; j++) {
                    float v = vv[j] + bias[gcol + j];
                    float u = 0.7978845608028654f * (v + 0.044715f * v * v * v);
                    float g = 0.5f * v * (1.f + tanhf(u));
                    split2h(g, hh[j], ll[j]);
                }
                *(__half2*)&Csp[o]     = __halves2half2(hh[0], hh[1]);
                *(__half2*)&Csp[o + 2] = __halves2half2(hh[2], hh[3]);
                size_t o2 = o + (size_t)ROWS * Ncols;
                *(__half2*)&Csp[o2]     = __halves2half2(ll[0], ll[1]);
                *(__half2*)&Csp[o2 + 2] = __halves2half2(ll[2], ll[3]);
            } else if (EPI == 2) {
                int bI = grow >> 12;
                float4 cur = *(const float4*)&C[o];
                const float* gp = gate + (size_t)bI * ADA + gcol;
                float b0 = bias ? bias[gcol + 0] : 0.f;
                float b1 = bias ? bias[gcol + 1] : 0.f;
                float b2 = bias ? bias[gcol + 2] : 0.f;
                float b3 = bias ? bias[gcol + 3] : 0.f;
                cur.x += gp[0] * (v0 + b0);
                cur.y += gp[1] * (v1 + b1);
                cur.z += gp[2] * (v2 + b2);
                cur.w += gp[3] * (v3 + b3);
                *(float4*)&C[o] = cur;
            } else {
                float4 res = *(const float4*)&resid[o];
                res.x += v0 + bias[gcol + 0];
                res.y += v1 + bias[gcol + 1];
                res.z += v2 + bias[gcol + 2];
                res.w += v3 + bias[gcol + 3];
                *(float4*)&C[o] = res;
            }
        }
        __syncthreads();
    }
    if (wid == 0) { TCGEN05_RELINQUISH(); TCGEN05_DEALLOC(tmem, 512); }
#else
    // generic-arch compile-only fallback
    const __half* Bhi = Wsp;
    const __half* Blo = Wsp + (size_t)Ncols * Kdim;
    for (int e = tid; e < 256 * 192; e += 256) {
        int r = e / 192, cI = e % 192;
        int grow = row0 + r;
        int ar = grow;
        if (EPI == 3) { int bb = ar >> 12, tt = (ar >> 8) & 15, nn = ar & 255; ar = ((bb << 8) + nn) * 16 + tt; }
        int gcol = col0 + cI;
        float acc = 0.f;
        for (int k = 0; k < Kdim; k++)
            acc += (__half2float(A[(size_t)ar * Kdim + k]) + __half2float(A[aPlane + (size_t)ar * Kdim + k])) *
                   (__half2float(Bhi[(size_t)gcol * Kdim + k]) + __half2float(Blo[(size_t)gcol * Kdim + k]));
        size_t o = (size_t)grow * Ncols + gcol;
        if (EPI == 0 && !SPL) C[o] = acc;
        else if ((EPI == 0 && SPL) || EPI == 1) {
            float g = acc;
            if (EPI == 1) {
                float v = acc + bias[gcol];
                float u = 0.7978845608028654f * (v + 0.044715f * v * v * v);
                g = 0.5f * v * (1.f + tanhf(u));
            }
            __half h, l; split2h(g, h, l);
            Csp[o] = h;
            Csp[o + (size_t)ROWS * Ncols] = l;
        } else if (EPI == 2) {
            int bI = grow >> 12;
            float bbv = bias ? bias[gcol] : 0.f;
            C[o] = C[o] + gate[(size_t)bI * ADA + gcol] * (acc + bbv);
        } else {
            C[o] = resid[o] + acc + bias[gcol];
        }
    }
#endif
}

// ---------------- temporal attention (fp16 hi/lo output) ----------------
__global__ __launch_bounds__(512)
void tattn_k(const float* __restrict__ qkv, const float* __restrict__ ckr,
             const float* __restrict__ cv, const int* __restrict__ f,
             __half* __restrict__ out) {
    __shared__ float Qs[16][72];
    __shared__ float Ks[32][73];
    __shared__ float Vs[32][73];
    __shared__ float Ps[16][32];
    int blk = blockIdx.x;
    int h = blk & 15;
    int bn = blk >> 4;
    int b = bn >> 8;
    int tid = threadIdx.x;
    for (int idx = tid; idx < 16 * 72; idx += 512) {
        int t = idx / 72, d = idx - t * 72;
        size_t base = ((size_t)(bn * 16 + t)) * M3 + h * 72 + d;
        Qs[t][d]      = qkv[base] * QK_SCALE;
        Ks[16 + t][d] = qkv[base + Mc];
        Vs[16 + t][d] = qkv[base + 2 * Mc];
        size_t cb = ((size_t)(b * 16 + t)) * Mc + h * 72 + d;
        Ks[t][d] = ckr[cb];
        Vs[t][d] = cv[cb];
    }
    __syncthreads();
    for (int idx = tid; idx < 16 * 36; idx += 512) {
        int t = idx / 36, i = idx - t * 36;
        float inv = expf(-LN10000 * (float)(2 * i) * (1.f / 72.f));
        float ang = (float)f[t] * inv;
        float cs = cosf(ang), sn = sinf(ang);
        float q0 = Qs[t][2 * i], q1 = Qs[t][2 * i + 1];
        Qs[t][2 * i]     = q0 * cs - q1 * sn;
        Qs[t][2 * i + 1] = q1 * cs + q0 * sn;
        float k0 = Ks[16 + t][2 * i], k1 = Ks[16 + t][2 * i + 1];
        Ks[16 + t][2 * i]     = k0 * cs - k1 * sn;
        Ks[16 + t][2 * i + 1] = k1 * cs + k0 * sn;
    }
    __syncthreads();
    int w = tid >> 5, lane = tid & 31;
    float a = 0.f;
#pragma unroll
    for (int d = 0; d < 72; d++) a += Qs[w][d] * Ks[lane][d];
    float mx = a;
    for (int o = 16; o > 0; o >>= 1) mx = fmaxf(mx, __shfl_xor_sync(0xffffffffu, mx, o));
    float e = expf(a - mx);
    float s = e;
    for (int o = 16; o > 0; o >>= 1) s += __shfl_xor_sync(0xffffffffu, s, o);
    Ps[w][lane] = e / s;
    __syncthreads();
    for (int idx = tid; idx < 16 * 72; idx += 512) {
        int t = idx / 72, d = idx - t * 72;
        float o = 0.f;
#pragma unroll
        for (int j = 0; j < 32; j++) o += Ps[t][j] * Vs[j][d];
        size_t oo = ((size_t)(bn * 16 + t)) * Mc + h * 72 + d;
        __half hh, ll;
        split2h(o, hh, ll);
        out[oo] = hh;
        out[oo + (size_t)ROWS * Mc] = ll;
    }
}

// ---------------- spatial attention (fp16 hi/lo output) ----------------
__global__ __launch_bounds__(256)
void sattn_k(const float* __restrict__ qkv2, const float* __restrict__ sk,
             const float* __restrict__ sv, __half* __restrict__ out) {
    __shared__ float Qs[32][72];
    __shared__ float L[32][257];
    int qt = blockIdx.x;
    int bth = blockIdx.y;
    int h = bth & 15, bt = bth >> 4;
    int tid = threadIdx.x;
    for (int idx = tid; idx < 32 * 72; idx += 256) {
        int q = idx / 72, d = idx - q * 72;
        int n = qt * 32 + q;
        Qs[q][d] = qkv2[((size_t)(bt * 256 + n)) * M3 + h * 72 + d] * QK_SCALE;
    }
    __syncthreads();
    int q = tid >> 3, g = tid & 7;
    for (int j = g; j < 257; j += 8) {
        const float* kp = (j == 0)
            ? (sk + (size_t)bt * Mc + h * 72)
            : (qkv2 + ((size_t)(bt * 256 + (j - 1))) * M3 + Mc + h * 72);
        float a = 0.f;
#pragma unroll
        for (int d = 0; d < 72; d++) a += Qs[q][d] * kp[d];
        L[q][j] = a;
    }
    float mx = -1e30f;
    for (int j = g; j < 257; j += 8) mx = fmaxf(mx, L[q][j]);
    for (int o = 4; o > 0; o >>= 1) mx = fmaxf(mx, __shfl_xor_sync(0xffffffffu, mx, o));
    float s = 0.f;
    for (int j = g; j < 257; j += 8) { float e = expf(L[q][j] - mx); L[q][j] = e; s += e; }
    for (int o = 4; o > 0; o >>= 1) s += __shfl_xor_sync(0xffffffffu, s, o);
    float invs = 1.f / s;
    __syncwarp();
    int d0 = g * 9;
    float o9[9];
#pragma unroll
    for (int i = 0; i < 9; i++) o9[i] = 0.f;
    for (int j = 0; j < 257; j++) {
        float p = L[q][j] * invs;
        const float* vp = (j == 0)
            ? (sv + (size_t)bt * Mc + h * 72 + d0)
            : (qkv2 + ((size_t)(bt * 256 + (j - 1))) * M3 + 2 * Mc + h * 72 + d0);
#pragma unroll
        for (int i = 0; i < 9; i++) o9[i] += p * vp[i];
    }
    int n = qt * 32 + q;
    size_t ob = ((size_t)(bt * 256 + n)) * Mc + h * 72 + d0;
#pragma unroll
    for (int i = 0; i < 9; i++) {
        __half hh, ll;
        split2h(o9[i], hh, ll);
        out[ob + i] = hh;
        out[ob + i + (size_t)ROWS * Mc] = ll;
    }
}

// ---------------- launch ----------------
extern "C" void kernel_launch(void* const* d_in, const int* in_sizes, int n_in,
                              void* d_out, int out_size) {
    const float* x      = (const float*)d_in[0];
    const float* c4t    = (const float*)d_in[1];
    const float* c      = (const float*)d_in[2];
    const float* W_ada  = (const float*)d_in[3];
    const float* b_ada  = (const float*)d_in[4];
    const float* tn_w   = (const float*)d_in[5];
    const float* tn_b   = (const float*)d_in[6];
    const float* t_qkv  = (const float*)d_in[7];
    const float* t_k    = (const float*)d_in[8];
    const float* t_v    = (const float*)d_in[9];
    const float* t_out  = (const float*)d_in[10];
    const float* t_fc_w = (const float*)d_in[11];
    const float* t_fc_b = (const float*)d_in[12];
    const float* s_qkv  = (const float*)d_in[13];
    const float* s_k    = (const float*)d_in[14];
    const float* s_v    = (const float*)d_in[15];
    const float* s_out  = (const float*)d_in[16];
    const float* mlp_w1 = (const float*)d_in[17];
    const float* mlp_b1 = (const float*)d_in[18];
    const float* mlp_w2 = (const float*)d_in[19];
    const float* mlp_b2 = (const float*)d_in[20];
    const int*   f      = (const int*)d_in[21];
    float* out = (float*)d_out;

    float *p_silu, *p_ada, *p_ckr, *p_cv, *p_sk, *p_sv, *p_qkv;
    __half *p_xt, *p_tout, *p_proj, *p_mod, *p_satt, *p_h;
    __half *w_tqkv, *w_sqkv, *w_tout, *w_tfc, *w_sout, *w_w1, *w_w2;
    cudaGetSymbolAddress((void**)&p_silu, g_silu);
    cudaGetSymbolAddress((void**)&p_ada,  g_ada);
    cudaGetSymbolAddress((void**)&p_ckr,  g_ckr);
    cudaGetSymbolAddress((void**)&p_cv,   g_cv);
    cudaGetSymbolAddress((void**)&p_sk,   g_sk);
    cudaGetSymbolAddress((void**)&p_sv,   g_sv);
    cudaGetSymbolAddress((void**)&p_xt,   g_xt);
    cudaGetSymbolAddress((void**)&p_qkv,  g_qkv);
    cudaGetSymbolAddress((void**)&p_tout, g_tout);
    cudaGetSymbolAddress((void**)&p_proj, g_proj);
    cudaGetSymbolAddress((void**)&p_mod,  g_mod);
    cudaGetSymbolAddress((void**)&p_satt, g_satt);
    cudaGetSymbolAddress((void**)&p_h,    g_h);
    cudaGetSymbolAddress((void**)&w_tqkv, gw_tqkv);
    cudaGetSymbolAddress((void**)&w_sqkv, gw_sqkv);
    cudaGetSymbolAddress((void**)&w_tout, gw_tout);
    cudaGetSymbolAddress((void**)&w_tfc,  gw_tfc);
    cudaGetSymbolAddress((void**)&w_sout, gw_sout);
    cudaGetSymbolAddress((void**)&w_w1,   gw_w1);
    cudaGetSymbolAddress((void**)&w_w2,   gw_w2);

    cudaFuncSetAttribute(tc_gemm<0,0>, cudaFuncAttributeMaxDynamicSharedMemorySize, GEMM_SMEM);
    cudaFuncSetAttribute(tc_gemm<0,1>, cudaFuncAttributeMaxDynamicSharedMemorySize, GEMM_SMEM);
    cudaFuncSetAttribute(tc_gemm<1,1>, cudaFuncAttributeMaxDynamicSharedMemorySize, GEMM_SMEM);
    cudaFuncSetAttribute(tc_gemm<2,0>, cudaFuncAttributeMaxDynamicSharedMemorySize, GEMM_SMEM);
    cudaFuncSetAttribute(tc_gemm<3,0>, cudaFuncAttributeMaxDynamicSharedMemorySize, GEMM_SMEM);

    const size_t plM = (size_t)ROWS * Mc;
    const size_t plF = (size_t)ROWS * FFD;

    // weight preprocessing: transpose + fp16 hi/lo split
    wsplit_k<<<dim3(M3 / 32, Mc / 32), 256>>>(t_qkv, Mc, M3, w_tqkv);
    wsplit_k<<<dim3(M3 / 32, Mc / 32), 256>>>(s_qkv, Mc, M3, w_sqkv);
    wsplit_k<<<dim3(Mc / 32, Mc / 32), 256>>>(t_out, Mc, Mc, w_tout);
    wsplit_k<<<dim3(Mc / 32, Mc / 32), 256>>>(t_fc_w, Mc, Mc, w_tfc);
    wsplit_k<<<dim3(Mc / 32, Mc / 32), 256>>>(s_out, Mc, Mc, w_sout);
    wsplit_k<<<dim3(FFD / 32, Mc / 32), 256>>>(mlp_w1, Mc, FFD, w_w1);
    wsplit_k<<<dim3(Mc / 32, FFD / 32), 256>>>(mlp_w2, FFD, Mc, w_w2);

    // adaLN + conditioning
    silu_k<<<9, 256>>>(c4t, p_silu);
    ada_k<<<dim3(27, 2), 256>>>(p_silu, W_ada, b_ada, p_ada);
    cproj4_k<<<dim3(9, 32, 4), 128>>>(c, t_k, t_v, s_k, s_v, p_ckr, p_cv, p_sk, p_sv);
    rotc_k<<<32, 256>>>(p_ckr, f);
    // temporal branch
    ln1_k<<<ROWS, 256>>>(x, tn_w, tn_b, p_xt);
    tc_gemm<0,0><<<dim3(18, 32), 256, GEMM_SMEM>>>(p_xt, plM, w_tqkv, p_qkv, nullptr, M3, Mc, nullptr, nullptr, nullptr);
    tattn_k<<<ROWS, 512>>>(p_qkv, p_ckr, p_cv, f, p_tout);
    tc_gemm<0,1><<<dim3(6, 32), 256, GEMM_SMEM>>>(p_tout, plM, w_tout, nullptr, p_proj, Mc, Mc, nullptr, nullptr, nullptr);
    tc_gemm<3,0><<<dim3(6, 32), 256, GEMM_SMEM>>>(p_proj, plM, w_tfc, out, nullptr, Mc, Mc, t_fc_b, x, nullptr);
    // spatial branch
    lnmod_k<<<ROWS, 256>>>(out, p_ada, 0, Mc, 1e-6f, p_mod);
    tc_gemm<0,0><<<dim3(18, 32), 256, GEMM_SMEM>>>(p_mod, plM, w_sqkv, p_qkv, nullptr, M3, Mc, nullptr, nullptr, nullptr);
    sattn_k<<<dim3(8, 512), 256>>>(p_qkv, p_sk, p_sv, p_satt);
    tc_gemm<2,0><<<dim3(6, 32), 256, GEMM_SMEM>>>(p_satt, plM, w_sout, out, nullptr, Mc, Mc, nullptr, nullptr, p_ada + 2 * Mc);
    // MLP
    lnmod_k<<<ROWS, 256>>>(out, p_ada, 3 * Mc, 4 * Mc, 1e-6f, p_mod);
    tc_gemm<1,1><<<dim3(24, 32), 256, GEMM_SMEM>>>(p_mod, plM, w_w1, nullptr, p_h, FFD, Mc, mlp_b1, nullptr, nullptr);
    tc_gemm<2,0><<<dim3(6, 32), 256, GEMM_SMEM>>>(p_h, plF, w_w2, out, nullptr, Mc, FFD, mlp_b2, nullptr, p_ada + 5 * Mc);
}